// round 3
// baseline (speedup 1.0000x reference)
#include <cuda_runtime.h>
#include <cuda_bf16.h>
#include <cuda_fp16.h>
#include <math.h>
#include <stdint.h>

#define VOCAB 32000
#define HID   256
#define BATCH 8
#define SEQ   256
#define MROWS (BATCH*SEQ)   // 2048

// Scratch (no allocation allowed): x_pre and hs, each [2048, 256] fp32 = 2 MB.
__device__ __align__(16) float g_xpre[MROWS * HID];
__device__ __align__(16) float g_hs[MROWS * HID];

__device__ __forceinline__ uint32_t pack_bf16(float a, float b) {
    __nv_bfloat162 t = __floats2bfloat162_rn(a, b);   // .x = a (low 16 bits)
    return *reinterpret_cast<uint32_t*>(&t);
}

// split pack: hi = bf16(a), lo = bf16(a - float(hi))  (a - hi exact in fp32)
__device__ __forceinline__ void pack_bf16_split(float a, float b,
                                                uint32_t& hi, uint32_t& lo) {
    __nv_bfloat16 ah = __float2bfloat16_rn(a);
    __nv_bfloat16 bh = __float2bfloat16_rn(b);
    float alo = a - __bfloat162float(ah);
    float blo = b - __bfloat162float(bh);
    __nv_bfloat162 th; th.x = ah; th.y = bh;
    hi = *reinterpret_cast<uint32_t*>(&th);
    lo = pack_bf16(alo, blo);
}

__device__ __forceinline__ uint32_t pack_fp16(float a, float b) {
    __half2 t = __floats2half2_rn(a, b);
    return *reinterpret_cast<uint32_t*>(&t);
}

__device__ __forceinline__ void mma16816(float* d, const uint32_t* a, const uint32_t* b) {
    asm volatile(
        "mma.sync.aligned.m16n8k16.row.col.f32.bf16.bf16.f32 "
        "{%0,%1,%2,%3}, {%4,%5,%6,%7}, {%8,%9}, {%0,%1,%2,%3};\n"
        : "+f"(d[0]), "+f"(d[1]), "+f"(d[2]), "+f"(d[3])
        : "r"(a[0]), "r"(a[1]), "r"(a[2]), "r"(a[3]),
          "r"(b[0]), "r"(b[1]));
}

// ---------------------------------------------------------------------------
// C[M,N] = A[M,K] (row-major) * B[N,K]^T (row-major, K contiguous) + bias
// fp32 in gmem, bf16 in smem, fp32 accumulate via mma.sync.
// SPLIT=true: error-free hi/lo bf16 decomposition of BOTH operands with
// 3 mmas (hi*hi + hi*lo + lo*hi) -> ~fp32-accurate product (for x_pre).
// BM=64, BN=128, BK=32, 8 warps in WM=2 x WN=4, warp tile 32x32.
// ---------------------------------------------------------------------------
template<int BM, int BN, int BK, int WM, int WN, bool SPLIT>
__global__ __launch_bounds__(256) void gemm_bias_kernel(
    const float* __restrict__ A, const float* __restrict__ B,
    const float* __restrict__ bias0, const float* __restrict__ bias1,
    float* __restrict__ C, int M, int N, int K)
{
    constexpr int TM = BM / WM, TN = BN / WN;     // 32 x 32
    constexpr int FM = TM / 16, FN = TN / 8;      // 2 x 4
    constexpr int SAW = BK / 2 + 1;               // u32 pairs per row + pad
    constexpr int AITER = BM * BK / (4 * 256);    // float4 loads per thread
    constexpr int BITER = BN * BK / (4 * 256);
    constexpr int NSEG = SPLIT ? 2 : 1;           // hi(+lo) segments

    __shared__ uint32_t As[NSEG][BM][SAW];
    __shared__ uint32_t Bs[NSEG][BN][SAW];

    const int tid     = threadIdx.x;
    const int rowTile = blockIdx.x * BM;
    const int colTile = blockIdx.y * BN;
    const int warp = tid >> 5, lane = tid & 31;
    const int wm = warp % WM, wn = warp / WM;
    const int g = lane >> 2, tg = lane & 3;

    float acc[FM][FN][4];
    #pragma unroll
    for (int i = 0; i < FM; i++)
        #pragma unroll
        for (int j = 0; j < FN; j++)
            #pragma unroll
            for (int u = 0; u < 4; u++) acc[i][j][u] = 0.f;

    float4 aReg[AITER], bReg[BITER];
    #pragma unroll
    for (int i = 0; i < AITER; i++) {
        int idx = tid + i * 256; int r = idx >> 3, q = idx & 7;
        aReg[i] = *reinterpret_cast<const float4*>(A + (size_t)(rowTile + r) * K + q * 4);
    }
    #pragma unroll
    for (int i = 0; i < BITER; i++) {
        int idx = tid + i * 256; int r = idx >> 3, q = idx & 7;
        bReg[i] = *reinterpret_cast<const float4*>(B + (size_t)(colTile + r) * K + q * 4);
    }

    for (int k0 = 0; k0 < K; k0 += BK) {
        // stage current regs into smem (fp32 -> bf16 [hi(,lo)])
        #pragma unroll
        for (int i = 0; i < AITER; i++) {
            int idx = tid + i * 256; int r = idx >> 3, q = idx & 7;
            if constexpr (SPLIT) {
                uint32_t h0, l0, h1, l1;
                pack_bf16_split(aReg[i].x, aReg[i].y, h0, l0);
                pack_bf16_split(aReg[i].z, aReg[i].w, h1, l1);
                As[0][r][q * 2] = h0; As[0][r][q * 2 + 1] = h1;
                As[1][r][q * 2] = l0; As[1][r][q * 2 + 1] = l1;
            } else {
                As[0][r][q * 2]     = pack_bf16(aReg[i].x, aReg[i].y);
                As[0][r][q * 2 + 1] = pack_bf16(aReg[i].z, aReg[i].w);
            }
        }
        #pragma unroll
        for (int i = 0; i < BITER; i++) {
            int idx = tid + i * 256; int r = idx >> 3, q = idx & 7;
            if constexpr (SPLIT) {
                uint32_t h0, l0, h1, l1;
                pack_bf16_split(bReg[i].x, bReg[i].y, h0, l0);
                pack_bf16_split(bReg[i].z, bReg[i].w, h1, l1);
                Bs[0][r][q * 2] = h0; Bs[0][r][q * 2 + 1] = h1;
                Bs[1][r][q * 2] = l0; Bs[1][r][q * 2 + 1] = l1;
            } else {
                Bs[0][r][q * 2]     = pack_bf16(bReg[i].x, bReg[i].y);
                Bs[0][r][q * 2 + 1] = pack_bf16(bReg[i].z, bReg[i].w);
            }
        }
        __syncthreads();

        // prefetch next k-tile (overlaps with mma below)
        if (k0 + BK < K) {
            #pragma unroll
            for (int i = 0; i < AITER; i++) {
                int idx = tid + i * 256; int r = idx >> 3, q = idx & 7;
                aReg[i] = *reinterpret_cast<const float4*>(
                    A + (size_t)(rowTile + r) * K + (k0 + BK) + q * 4);
            }
            #pragma unroll
            for (int i = 0; i < BITER; i++) {
                int idx = tid + i * 256; int r = idx >> 3, q = idx & 7;
                bReg[i] = *reinterpret_cast<const float4*>(
                    B + (size_t)(colTile + r) * K + (k0 + BK) + q * 4);
            }
        }

        #pragma unroll
        for (int kt = 0; kt < BK / 16; kt++) {
            const int kp = kt * 8;  // pair offset of k16 chunk
            uint32_t afr[NSEG][FM][4];
            #pragma unroll
            for (int s = 0; s < NSEG; s++)
                #pragma unroll
                for (int fm = 0; fm < FM; fm++) {
                    int r = wm * TM + fm * 16 + g;
                    afr[s][fm][0] = As[s][r][kp + tg];
                    afr[s][fm][1] = As[s][r + 8][kp + tg];
                    afr[s][fm][2] = As[s][r][kp + tg + 4];
                    afr[s][fm][3] = As[s][r + 8][kp + tg + 4];
                }
            uint32_t bfr[NSEG][FN][2];
            #pragma unroll
            for (int s = 0; s < NSEG; s++)
                #pragma unroll
                for (int fn = 0; fn < FN; fn++) {
                    int c = wn * TN + fn * 8 + g;
                    bfr[s][fn][0] = Bs[s][c][kp + tg];
                    bfr[s][fn][1] = Bs[s][c][kp + tg + 4];
                }
            #pragma unroll
            for (int fm = 0; fm < FM; fm++)
                #pragma unroll
                for (int fn = 0; fn < FN; fn++) {
                    mma16816(acc[fm][fn], afr[0][fm], bfr[0][fn]);   // hi*hi
                    if constexpr (SPLIT) {
                        mma16816(acc[fm][fn], afr[0][fm], bfr[1][fn]); // hi*lo
                        mma16816(acc[fm][fn], afr[1][fm], bfr[0][fn]); // lo*hi
                    }
                }
        }
        __syncthreads();
    }

    // epilogue: add bias, write fp32
    #pragma unroll
    for (int fm = 0; fm < FM; fm++) {
        #pragma unroll
        for (int fn = 0; fn < FN; fn++) {
            int r = rowTile + wm * TM + fm * 16 + g;
            int c = colTile + wn * TN + fn * 8 + tg * 2;
            float b0v = bias0[c]     + (bias1 ? bias1[c]     : 0.f);
            float b1v = bias0[c + 1] + (bias1 ? bias1[c + 1] : 0.f);
            C[(size_t)r * N + c]           = acc[fm][fn][0] + b0v;
            C[(size_t)r * N + c + 1]       = acc[fm][fn][1] + b1v;
            C[(size_t)(r + 8) * N + c]     = acc[fm][fn][2] + b0v;
            C[(size_t)(r + 8) * N + c + 1] = acc[fm][fn][3] + b1v;
        }
    }
}

// ---------------------------------------------------------------------------
// Recurrence: one CTA per batch element, 256 threads (thread i -> h[i]).
// W_hh held in SMEM as fp16 pairs [256][129 u32] (pad -> conflict-free),
// h in SMEM fp32; fp32 accumulate.
// ---------------------------------------------------------------------------
#define RNN_SMEM (256*129*4 + 256*4)

__global__ __launch_bounds__(256) void rnn_kernel(
    const float* __restrict__ W_hh, const float* __restrict__ h0,
    const float* __restrict__ xpre, float* __restrict__ hs,
    float* __restrict__ hlast)
{
    extern __shared__ uint32_t smem[];
    uint32_t* Wp = smem;                                   // [256][129]
    float* h = reinterpret_cast<float*>(smem + 256 * 129); // [256]
    const int tid = threadIdx.x, b = blockIdx.x;

    for (int idx = tid; idx < 256 * 128; idx += 256) {
        int r = idx >> 7, p = idx & 127;
        const float2 wv = *reinterpret_cast<const float2*>(W_hh + r * 256 + 2 * p);
        Wp[r * 129 + p] = pack_fp16(wv.x, wv.y);
    }
    h[tid] = h0[b * HID + tid];
    __syncthreads();

    const float* xp  = xpre + (size_t)b * SEQ * HID;
    float* hrow      = hs   + (size_t)b * SEQ * HID;
    const uint32_t* wrow = Wp + tid * 129;

    float xnext = xp[tid];
    for (int t = 0; t < SEQ; t++) {
        float xc = xnext;
        if (t + 1 < SEQ) xnext = xp[(t + 1) * HID + tid];
        float a0 = 0.f, a1 = 0.f, a2 = 0.f, a3 = 0.f;
        #pragma unroll 16
        for (int p = 0; p < 128; p += 2) {
            uint32_t w0 = wrow[p], w1 = wrow[p + 1];
            float4 hv = *reinterpret_cast<const float4*>(h + 2 * p);  // broadcast
            float2 f0 = __half22float2(*reinterpret_cast<__half2*>(&w0));
            float2 f1 = __half22float2(*reinterpret_cast<__half2*>(&w1));
            a0 = fmaf(hv.x, f0.x, a0);
            a1 = fmaf(hv.y, f0.y, a1);
            a2 = fmaf(hv.z, f1.x, a2);
            a3 = fmaf(hv.w, f1.y, a3);
        }
        float hn = tanhf(xc + ((a0 + a1) + (a2 + a3)));
        __syncthreads();
        h[tid] = hn;
        __syncthreads();
        hrow[t * HID + tid] = hn;
    }
    if (hlast) hlast[b * HID + tid] = h[tid];
}

// ---------------------------------------------------------------------------
// In-place log_softmax over each row of d_out[2048, 32000].
// ---------------------------------------------------------------------------
__global__ __launch_bounds__(256) void logsoftmax_kernel(float* __restrict__ out)
{
    const int row = blockIdx.x;
    float* x = out + (size_t)row * VOCAB;
    float4* x4 = reinterpret_cast<float4*>(x);
    const int N4 = VOCAB / 4;   // 8000
    const int tid = threadIdx.x;

    float m = -3.0e38f, s = 0.f;
    for (int j = tid; j < N4; j += 256) {
        float4 v = x4[j];
        float vals[4] = {v.x, v.y, v.z, v.w};
        #pragma unroll
        for (int u = 0; u < 4; u++) {
            float vv = vals[u];
            if (vv > m) { s = s * __expf(m - vv) + 1.f; m = vv; }
            else        { s += __expf(vv - m); }
        }
    }
    __shared__ float sm[256], ss[256];
    sm[tid] = m; ss[tid] = s;
    __syncthreads();
    for (int off = 128; off > 0; off >>= 1) {
        if (tid < off) {
            float m1 = sm[tid], s1 = ss[tid];
            float m2 = sm[tid + off], s2 = ss[tid + off];
            float mm = fmaxf(m1, m2);
            sm[tid] = mm;
            ss[tid] = s1 * __expf(m1 - mm) + s2 * __expf(m2 - mm);
        }
        __syncthreads();
    }
    const float L = sm[0] + logf(ss[0]);
    for (int j = tid; j < N4; j += 256) {
        float4 v = x4[j];
        v.x -= L; v.y -= L; v.z -= L; v.w -= L;
        x4[j] = v;
    }
}

// ---------------------------------------------------------------------------
extern "C" void kernel_launch(void* const* d_in, const int* in_sizes, int n_in,
                              void* d_out, int out_size)
{
    const float* input_seq = (const float*)d_in[0];  // [8,256,32000]
    const float* h0        = (const float*)d_in[1];  // [1,8,256]
    const float* W_ih      = (const float*)d_in[2];  // [256,32000]
    const float* W_hh      = (const float*)d_in[3];  // [256,256]
    const float* b_ih      = (const float*)d_in[4];  // [256]
    const float* b_hh      = (const float*)d_in[5];  // [256]
    const float* W_fc      = (const float*)d_in[6];  // [32000,256]
    const float* b_fc      = (const float*)d_in[7];  // [32000]
    float* out = (float*)d_out;

    float *xpre_ptr = nullptr, *hs_ptr = nullptr;
    cudaGetSymbolAddress((void**)&xpre_ptr, g_xpre);
    cudaGetSymbolAddress((void**)&hs_ptr, g_hs);

    // 1) x_pre = input_seq @ W_ih^T + b_ih + b_hh   [2048,256]
    //    SPLIT=true: 3xBF16 error-free-split -> ~fp32 accuracy (the
    //    recurrence integrates x_pre quantization noise 256x, so plain
    //    bf16 here blows the h_last tolerance).
    gemm_bias_kernel<64,128,32,2,4,true><<<dim3(MROWS/64, HID/128), 256>>>(
        input_seq, W_ih, b_ih, b_hh, xpre_ptr, MROWS, HID, VOCAB);

    // 2) recurrence -> hs [2048,256], h_last appended after log_probs
    cudaFuncSetAttribute(rnn_kernel,
                         cudaFuncAttributeMaxDynamicSharedMemorySize, RNN_SMEM);
    const long long logits_elems = (long long)MROWS * VOCAB;
    float* hlast = ((long long)out_size >= logits_elems + BATCH * HID)
                       ? out + (size_t)logits_elems : nullptr;
    rnn_kernel<<<BATCH, 256, RNN_SMEM>>>(W_hh, h0, xpre_ptr, hs_ptr, hlast);

    // 3) logits = hs @ W_fc^T + b_fc -> d_out (plain bf16 path passed at 2.4e-4)
    gemm_bias_kernel<64,128,32,2,4,false><<<dim3(MROWS/64, VOCAB/128), 256>>>(
        hs_ptr, W_fc, b_fc, nullptr, out, MROWS, VOCAB, HID);

    // 4) in-place log_softmax
    logsoftmax_kernel<<<MROWS, 256>>>(out);
}

// round 4
// speedup vs baseline: 1.4303x; 1.4303x over previous
#include <cuda_runtime.h>
#include <cuda_bf16.h>
#include <cuda_fp16.h>
#include <math.h>
#include <stdint.h>

#define VOCAB 32000
#define HID   256
#define BATCH 8
#define SEQ   256
#define MROWS (BATCH*SEQ)   // 2048
#define SPLITK 4
#define KCHUNK (VOCAB/SPLITK)  // 8000

// Scratch (no allocation allowed)
__device__ __align__(16) float g_xpre[MROWS * HID];              // 2 MB
__device__ __align__(16) float g_hs[MROWS * HID];                // 2 MB
__device__ __align__(16) float g_part[SPLITK * MROWS * HID];     // 8 MB
__device__ __align__(16) __nv_bfloat16 g_wih_hi[HID * VOCAB];    // 16.4 MB
__device__ __align__(16) __nv_bfloat16 g_wih_lo[HID * VOCAB];    // 16.4 MB

__device__ __forceinline__ uint32_t pack_bf16(float a, float b) {
    __nv_bfloat162 t = __floats2bfloat162_rn(a, b);   // .x = a (low 16 bits)
    return *reinterpret_cast<uint32_t*>(&t);
}

// split pack: hi = bf16(a), lo = bf16(a - float(hi))  (a - hi exact in fp32)
__device__ __forceinline__ void pack_bf16_split(float a, float b,
                                                uint32_t& hi, uint32_t& lo) {
    __nv_bfloat16 ah = __float2bfloat16_rn(a);
    __nv_bfloat16 bh = __float2bfloat16_rn(b);
    float alo = a - __bfloat162float(ah);
    float blo = b - __bfloat162float(bh);
    __nv_bfloat162 th; th.x = ah; th.y = bh;
    hi = *reinterpret_cast<uint32_t*>(&th);
    lo = pack_bf16(alo, blo);
}

__device__ __forceinline__ uint32_t pack_fp16(float a, float b) {
    __half2 t = __floats2half2_rn(a, b);
    return *reinterpret_cast<uint32_t*>(&t);
}

__device__ __forceinline__ void mma16816(float* d, const uint32_t* a, const uint32_t* b) {
    asm volatile(
        "mma.sync.aligned.m16n8k16.row.col.f32.bf16.bf16.f32 "
        "{%0,%1,%2,%3}, {%4,%5,%6,%7}, {%8,%9}, {%0,%1,%2,%3};\n"
        : "+f"(d[0]), "+f"(d[1]), "+f"(d[2]), "+f"(d[3])
        : "r"(a[0]), "r"(a[1]), "r"(a[2]), "r"(a[3]),
          "r"(b[0]), "r"(b[1]));
}

// ---------------------------------------------------------------------------
// Prep: W_ih fp32 -> (hi, lo) bf16 arrays, error-free split. Elementwise.
// ---------------------------------------------------------------------------
__global__ __launch_bounds__(256) void prep_wih_kernel(const float* __restrict__ W)
{
    int idx = (blockIdx.x * 256 + threadIdx.x) * 4;   // element index
    float4 v = *reinterpret_cast<const float4*>(W + idx);
    uint32_t h0, l0, h1, l1;
    pack_bf16_split(v.x, v.y, h0, l0);
    pack_bf16_split(v.z, v.w, h1, l1);
    uint2 hh = make_uint2(h0, h1), ll = make_uint2(l0, l1);
    *reinterpret_cast<uint2*>(g_wih_hi + idx) = hh;
    *reinterpret_cast<uint2*>(g_wih_lo + idx) = ll;
}

// ---------------------------------------------------------------------------
// GEMM1 with split-K: part[z] = A[:, zK:(z+1)K] * B[:, zK:(z+1)K]^T
// A fp32 (input_seq), B = preconverted bf16 hi/lo (W_ih). 3-mma split scheme.
// BM=64, BN=128, BK=32, 8 warps WM=2 x WN=4. Grid (M/64, N/128, SPLITK).
// ---------------------------------------------------------------------------
__global__ __launch_bounds__(256, 2) void gemm1_splitk_kernel(
    const float* __restrict__ A, float* __restrict__ part)
{
    constexpr int BM = 64, BN = 128, BK = 32;
    constexpr int SAW = 17;                 // 16 u32 pairs + 1 pad
    const int K = VOCAB, N = HID;

    __shared__ uint32_t As[2][BM][SAW];
    __shared__ uint32_t Bs[2][BN][SAW];

    const int tid = threadIdx.x;
    const int rowTile = blockIdx.x * BM;
    const int colTile = blockIdx.y * BN;
    const int kbase   = blockIdx.z * KCHUNK;
    const int warp = tid >> 5, lane = tid & 31;
    const int wm = warp % 2, wn = warp / 2;     // 2 x 4
    const int g = lane >> 2, tg = lane & 3;

    float acc[2][4][4];
    #pragma unroll
    for (int i = 0; i < 2; i++)
        #pragma unroll
        for (int j = 0; j < 4; j++)
            #pragma unroll
            for (int u = 0; u < 4; u++) acc[i][j][u] = 0.f;

    // A: 64 rows x 32 K fp32 = 512 float4; 2 per thread.
    // B: 128 rows x 16 u32-pairs per seg = 512 uint4 per seg; 2 per thread per seg.
    float4 aReg[2];
    uint4  bRegH[2], bRegL[2];

    #pragma unroll
    for (int i = 0; i < 2; i++) {
        int idx = tid + i * 256; int r = idx >> 3, q = idx & 7;
        aReg[i] = *reinterpret_cast<const float4*>(
            A + (size_t)(rowTile + r) * K + kbase + q * 4);
    }
    #pragma unroll
    for (int i = 0; i < 2; i++) {
        int idx = tid + i * 256; int r = idx >> 2, q = idx & 3;
        size_t off = (size_t)(colTile + r) * K + kbase + q * 8;
        bRegH[i] = *reinterpret_cast<const uint4*>(g_wih_hi + off);
        bRegL[i] = *reinterpret_cast<const uint4*>(g_wih_lo + off);
    }

    for (int k0 = 0; k0 < KCHUNK; k0 += BK) {
        #pragma unroll
        for (int i = 0; i < 2; i++) {
            int idx = tid + i * 256; int r = idx >> 3, q = idx & 7;
            uint32_t h0, l0, h1, l1;
            pack_bf16_split(aReg[i].x, aReg[i].y, h0, l0);
            pack_bf16_split(aReg[i].z, aReg[i].w, h1, l1);
            As[0][r][q * 2] = h0; As[0][r][q * 2 + 1] = h1;
            As[1][r][q * 2] = l0; As[1][r][q * 2 + 1] = l1;
        }
        #pragma unroll
        for (int i = 0; i < 2; i++) {
            int idx = tid + i * 256; int r = idx >> 2, q = idx & 3;
            Bs[0][r][q * 4 + 0] = bRegH[i].x; Bs[0][r][q * 4 + 1] = bRegH[i].y;
            Bs[0][r][q * 4 + 2] = bRegH[i].z; Bs[0][r][q * 4 + 3] = bRegH[i].w;
            Bs[1][r][q * 4 + 0] = bRegL[i].x; Bs[1][r][q * 4 + 1] = bRegL[i].y;
            Bs[1][r][q * 4 + 2] = bRegL[i].z; Bs[1][r][q * 4 + 3] = bRegL[i].w;
        }
        __syncthreads();

        if (k0 + BK < KCHUNK) {
            #pragma unroll
            for (int i = 0; i < 2; i++) {
                int idx = tid + i * 256; int r = idx >> 3, q = idx & 7;
                aReg[i] = *reinterpret_cast<const float4*>(
                    A + (size_t)(rowTile + r) * K + kbase + (k0 + BK) + q * 4);
            }
            #pragma unroll
            for (int i = 0; i < 2; i++) {
                int idx = tid + i * 256; int r = idx >> 2, q = idx & 3;
                size_t off = (size_t)(colTile + r) * K + kbase + (k0 + BK) + q * 8;
                bRegH[i] = *reinterpret_cast<const uint4*>(g_wih_hi + off);
                bRegL[i] = *reinterpret_cast<const uint4*>(g_wih_lo + off);
            }
        }

        #pragma unroll
        for (int kt = 0; kt < 2; kt++) {
            const int kp = kt * 8;
            uint32_t afr[2][2][4];
            #pragma unroll
            for (int s = 0; s < 2; s++)
                #pragma unroll
                for (int fm = 0; fm < 2; fm++) {
                    int r = wm * 32 + fm * 16 + g;
                    afr[s][fm][0] = As[s][r][kp + tg];
                    afr[s][fm][1] = As[s][r + 8][kp + tg];
                    afr[s][fm][2] = As[s][r][kp + tg + 4];
                    afr[s][fm][3] = As[s][r + 8][kp + tg + 4];
                }
            uint32_t bfr[2][4][2];
            #pragma unroll
            for (int s = 0; s < 2; s++)
                #pragma unroll
                for (int fn = 0; fn < 4; fn++) {
                    int c = wn * 32 + fn * 8 + g;
                    bfr[s][fn][0] = Bs[s][c][kp + tg];
                    bfr[s][fn][1] = Bs[s][c][kp + tg + 4];
                }
            #pragma unroll
            for (int fm = 0; fm < 2; fm++)
                #pragma unroll
                for (int fn = 0; fn < 4; fn++) {
                    mma16816(acc[fm][fn], afr[0][fm], bfr[0][fn]);   // hi*hi
                    mma16816(acc[fm][fn], afr[0][fm], bfr[1][fn]);   // hi*lo
                    mma16816(acc[fm][fn], afr[1][fm], bfr[0][fn]);   // lo*hi
                }
        }
        __syncthreads();
    }

    float* out = part + (size_t)blockIdx.z * MROWS * HID;
    #pragma unroll
    for (int fm = 0; fm < 2; fm++)
        #pragma unroll
        for (int fn = 0; fn < 4; fn++) {
            int r = rowTile + wm * 32 + fm * 16 + g;
            int c = colTile + wn * 32 + fn * 8 + tg * 2;
            out[(size_t)r * N + c]           = acc[fm][fn][0];
            out[(size_t)r * N + c + 1]       = acc[fm][fn][1];
            out[(size_t)(r + 8) * N + c]     = acc[fm][fn][2];
            out[(size_t)(r + 8) * N + c + 1] = acc[fm][fn][3];
        }
}

// ---------------------------------------------------------------------------
// Reduce split-K partials + biases -> x_pre.  Deterministic fixed-order sum.
// ---------------------------------------------------------------------------
__global__ __launch_bounds__(256) void reduce_xpre_kernel(
    const float* __restrict__ b_ih, const float* __restrict__ b_hh)
{
    const int idx4 = blockIdx.x * 256 + threadIdx.x;        // float4 index
    const int TOT4 = MROWS * HID / 4;                        // 131072
    const float4* p = reinterpret_cast<const float4*>(g_part);
    float4 v = p[idx4];
    #pragma unroll
    for (int z = 1; z < SPLITK; z++) {
        float4 w = p[idx4 + z * TOT4];
        v.x += w.x; v.y += w.y; v.z += w.z; v.w += w.w;
    }
    const int n4 = idx4 & (HID / 4 - 1);
    float4 b1 = reinterpret_cast<const float4*>(b_ih)[n4];
    float4 b2 = reinterpret_cast<const float4*>(b_hh)[n4];
    v.x += b1.x + b2.x; v.y += b1.y + b2.y;
    v.z += b1.z + b2.z; v.w += b1.w + b2.w;
    reinterpret_cast<float4*>(g_xpre)[idx4] = v;
}

// ---------------------------------------------------------------------------
// GEMM2: C[M,N] = A[M,K] * B[N,K]^T + bias (plain bf16 path, as before)
// ---------------------------------------------------------------------------
template<int BM, int BN, int BK, int WM, int WN>
__global__ __launch_bounds__(256) void gemm_bias_kernel(
    const float* __restrict__ A, const float* __restrict__ B,
    const float* __restrict__ bias0,
    float* __restrict__ C, int M, int N, int K)
{
    constexpr int TM = BM / WM, TN = BN / WN;
    constexpr int FM = TM / 16, FN = TN / 8;
    constexpr int SAW = BK / 2 + 1;
    constexpr int AITER = BM * BK / (4 * 256);
    constexpr int BITER = BN * BK / (4 * 256);

    __shared__ uint32_t As[BM][SAW];
    __shared__ uint32_t Bs[BN][SAW];

    const int tid     = threadIdx.x;
    const int rowTile = blockIdx.x * BM;
    const int colTile = blockIdx.y * BN;
    const int warp = tid >> 5, lane = tid & 31;
    const int wm = warp % WM, wn = warp / WM;
    const int g = lane >> 2, tg = lane & 3;

    float acc[FM][FN][4];
    #pragma unroll
    for (int i = 0; i < FM; i++)
        #pragma unroll
        for (int j = 0; j < FN; j++)
            #pragma unroll
            for (int u = 0; u < 4; u++) acc[i][j][u] = 0.f;

    float4 aReg[AITER], bReg[BITER];
    #pragma unroll
    for (int i = 0; i < AITER; i++) {
        int idx = tid + i * 256; int r = idx >> 3, q = idx & 7;
        aReg[i] = *reinterpret_cast<const float4*>(A + (size_t)(rowTile + r) * K + q * 4);
    }
    #pragma unroll
    for (int i = 0; i < BITER; i++) {
        int idx = tid + i * 256; int r = idx >> 3, q = idx & 7;
        bReg[i] = *reinterpret_cast<const float4*>(B + (size_t)(colTile + r) * K + q * 4);
    }

    for (int k0 = 0; k0 < K; k0 += BK) {
        #pragma unroll
        for (int i = 0; i < AITER; i++) {
            int idx = tid + i * 256; int r = idx >> 3, q = idx & 7;
            As[r][q * 2]     = pack_bf16(aReg[i].x, aReg[i].y);
            As[r][q * 2 + 1] = pack_bf16(aReg[i].z, aReg[i].w);
        }
        #pragma unroll
        for (int i = 0; i < BITER; i++) {
            int idx = tid + i * 256; int r = idx >> 3, q = idx & 7;
            Bs[r][q * 2]     = pack_bf16(bReg[i].x, bReg[i].y);
            Bs[r][q * 2 + 1] = pack_bf16(bReg[i].z, bReg[i].w);
        }
        __syncthreads();

        if (k0 + BK < K) {
            #pragma unroll
            for (int i = 0; i < AITER; i++) {
                int idx = tid + i * 256; int r = idx >> 3, q = idx & 7;
                aReg[i] = *reinterpret_cast<const float4*>(
                    A + (size_t)(rowTile + r) * K + (k0 + BK) + q * 4);
            }
            #pragma unroll
            for (int i = 0; i < BITER; i++) {
                int idx = tid + i * 256; int r = idx >> 3, q = idx & 7;
                bReg[i] = *reinterpret_cast<const float4*>(
                    B + (size_t)(colTile + r) * K + (k0 + BK) + q * 4);
            }
        }

        #pragma unroll
        for (int kt = 0; kt < BK / 16; kt++) {
            const int kp = kt * 8;
            uint32_t afr[FM][4];
            #pragma unroll
            for (int fm = 0; fm < FM; fm++) {
                int r = wm * TM + fm * 16 + g;
                afr[fm][0] = As[r][kp + tg];
                afr[fm][1] = As[r + 8][kp + tg];
                afr[fm][2] = As[r][kp + tg + 4];
                afr[fm][3] = As[r + 8][kp + tg + 4];
            }
            uint32_t bfr[FN][2];
            #pragma unroll
            for (int fn = 0; fn < FN; fn++) {
                int c = wn * TN + fn * 8 + g;
                bfr[fn][0] = Bs[c][kp + tg];
                bfr[fn][1] = Bs[c][kp + tg + 4];
            }
            #pragma unroll
            for (int fm = 0; fm < FM; fm++)
                #pragma unroll
                for (int fn = 0; fn < FN; fn++)
                    mma16816(acc[fm][fn], afr[fm], bfr[fn]);
        }
        __syncthreads();
    }

    #pragma unroll
    for (int fm = 0; fm < FM; fm++) {
        #pragma unroll
        for (int fn = 0; fn < FN; fn++) {
            int r = rowTile + wm * TM + fm * 16 + g;
            int c = colTile + wn * TN + fn * 8 + tg * 2;
            float b0v = bias0[c], b1v = bias0[c + 1];
            C[(size_t)r * N + c]           = acc[fm][fn][0] + b0v;
            C[(size_t)r * N + c + 1]       = acc[fm][fn][1] + b1v;
            C[(size_t)(r + 8) * N + c]     = acc[fm][fn][2] + b0v;
            C[(size_t)(r + 8) * N + c + 1] = acc[fm][fn][3] + b1v;
        }
    }
}

// ---------------------------------------------------------------------------
// Recurrence: one CTA per batch element, 256 threads (thread i -> h[i]).
// W_hh in SMEM as fp16 pairs; h in SMEM fp32; fp32 accumulate.
// ---------------------------------------------------------------------------
#define RNN_SMEM (256*129*4 + 256*4)

__global__ __launch_bounds__(256) void rnn_kernel(
    const float* __restrict__ W_hh, const float* __restrict__ h0,
    const float* __restrict__ xpre, float* __restrict__ hs,
    float* __restrict__ hlast)
{
    extern __shared__ uint32_t smem[];
    uint32_t* Wp = smem;                                   // [256][129]
    float* h = reinterpret_cast<float*>(smem + 256 * 129); // [256]
    const int tid = threadIdx.x, b = blockIdx.x;

    for (int idx = tid; idx < 256 * 128; idx += 256) {
        int r = idx >> 7, p = idx & 127;
        const float2 wv = *reinterpret_cast<const float2*>(W_hh + r * 256 + 2 * p);
        Wp[r * 129 + p] = pack_fp16(wv.x, wv.y);
    }
    h[tid] = h0[b * HID + tid];
    __syncthreads();

    const float* xp  = xpre + (size_t)b * SEQ * HID;
    float* hrow      = hs   + (size_t)b * SEQ * HID;
    const uint32_t* wrow = Wp + tid * 129;

    float xnext = xp[tid];
    for (int t = 0; t < SEQ; t++) {
        float xc = xnext;
        if (t + 1 < SEQ) xnext = xp[(t + 1) * HID + tid];
        float a0 = 0.f, a1 = 0.f, a2 = 0.f, a3 = 0.f;
        #pragma unroll 16
        for (int p = 0; p < 128; p += 2) {
            uint32_t w0 = wrow[p], w1 = wrow[p + 1];
            float4 hv = *reinterpret_cast<const float4*>(h + 2 * p);  // broadcast
            float2 f0 = __half22float2(*reinterpret_cast<__half2*>(&w0));
            float2 f1 = __half22float2(*reinterpret_cast<__half2*>(&w1));
            a0 = fmaf(hv.x, f0.x, a0);
            a1 = fmaf(hv.y, f0.y, a1);
            a2 = fmaf(hv.z, f1.x, a2);
            a3 = fmaf(hv.w, f1.y, a3);
        }
        float hn = tanhf(xc + ((a0 + a1) + (a2 + a3)));
        __syncthreads();
        h[tid] = hn;
        __syncthreads();
        hrow[t * HID + tid] = hn;
    }
    if (hlast) hlast[b * HID + tid] = h[tid];
}

// ---------------------------------------------------------------------------
// In-place log_softmax over each row of d_out[2048, 32000].
// ---------------------------------------------------------------------------
__global__ __launch_bounds__(256) void logsoftmax_kernel(float* __restrict__ out)
{
    const int row = blockIdx.x;
    float* x = out + (size_t)row * VOCAB;
    float4* x4 = reinterpret_cast<float4*>(x);
    const int N4 = VOCAB / 4;   // 8000
    const int tid = threadIdx.x;

    float m = -3.0e38f, s = 0.f;
    for (int j = tid; j < N4; j += 256) {
        float4 v = x4[j];
        float vals[4] = {v.x, v.y, v.z, v.w};
        #pragma unroll
        for (int u = 0; u < 4; u++) {
            float vv = vals[u];
            if (vv > m) { s = s * __expf(m - vv) + 1.f; m = vv; }
            else        { s += __expf(vv - m); }
        }
    }
    __shared__ float sm[256], ss[256];
    sm[tid] = m; ss[tid] = s;
    __syncthreads();
    for (int off = 128; off > 0; off >>= 1) {
        if (tid < off) {
            float m1 = sm[tid], s1 = ss[tid];
            float m2 = sm[tid + off], s2 = ss[tid + off];
            float mm = fmaxf(m1, m2);
            sm[tid] = mm;
            ss[tid] = s1 * __expf(m1 - mm) + s2 * __expf(m2 - mm);
        }
        __syncthreads();
    }
    const float L = sm[0] + logf(ss[0]);
    for (int j = tid; j < N4; j += 256) {
        float4 v = x4[j];
        v.x -= L; v.y -= L; v.z -= L; v.w -= L;
        x4[j] = v;
    }
}

// ---------------------------------------------------------------------------
extern "C" void kernel_launch(void* const* d_in, const int* in_sizes, int n_in,
                              void* d_out, int out_size)
{
    const float* input_seq = (const float*)d_in[0];  // [8,256,32000]
    const float* h0        = (const float*)d_in[1];  // [1,8,256]
    const float* W_ih      = (const float*)d_in[2];  // [256,32000]
    const float* W_hh      = (const float*)d_in[3];  // [256,256]
    const float* b_ih      = (const float*)d_in[4];  // [256]
    const float* b_hh      = (const float*)d_in[5];  // [256]
    const float* W_fc      = (const float*)d_in[6];  // [32000,256]
    const float* b_fc      = (const float*)d_in[7];  // [32000]
    float* out = (float*)d_out;

    float *xpre_ptr = nullptr, *hs_ptr = nullptr, *part_ptr = nullptr;
    cudaGetSymbolAddress((void**)&xpre_ptr, g_xpre);
    cudaGetSymbolAddress((void**)&hs_ptr, g_hs);
    cudaGetSymbolAddress((void**)&part_ptr, g_part);

    // 0) W_ih -> (hi, lo) bf16, once per launch (graph-replayed; cheap ~10us)
    prep_wih_kernel<<<HID * VOCAB / (256 * 4), 256>>>(W_ih);

    // 1) split-K GEMM1: partials = input_seq @ W_ih^T (3xBF16 split scheme)
    gemm1_splitk_kernel<<<dim3(MROWS/64, HID/128, SPLITK), 256>>>(
        input_seq, part_ptr);

    // 1b) reduce partials + biases -> x_pre
    reduce_xpre_kernel<<<MROWS * HID / (4 * 256), 256>>>(b_ih, b_hh);

    // 2) recurrence -> hs [2048,256], h_last appended after log_probs
    cudaFuncSetAttribute(rnn_kernel,
                         cudaFuncAttributeMaxDynamicSharedMemorySize, RNN_SMEM);
    const long long logits_elems = (long long)MROWS * VOCAB;
    float* hlast = ((long long)out_size >= logits_elems + BATCH * HID)
                       ? out + (size_t)logits_elems : nullptr;
    rnn_kernel<<<BATCH, 256, RNN_SMEM>>>(W_hh, h0, xpre_ptr, hs_ptr, hlast);

    // 3) logits = hs @ W_fc^T + b_fc -> d_out (plain bf16 path)
    gemm_bias_kernel<64,128,32,2,4><<<dim3(MROWS/64, VOCAB/128), 256>>>(
        hs_ptr, W_fc, b_fc, out, MROWS, VOCAB, HID);

    // 4) in-place log_softmax
    logsoftmax_kernel<<<MROWS, 256>>>(out);
}

// round 5
// speedup vs baseline: 1.7612x; 1.2313x over previous
#include <cuda_runtime.h>
#include <cuda_bf16.h>
#include <cuda_fp16.h>
#include <math.h>
#include <stdint.h>

#define VOCAB 32000
#define HID   256
#define BATCH 8
#define SEQ   256
#define MROWS (BATCH*SEQ)   // 2048
#define SPLITK 4
#define KCHUNK (VOCAB/SPLITK)  // 8000

typedef unsigned long long ull;

// Scratch (no allocation allowed)
__device__ __align__(16) float g_xpre[MROWS * HID];              // 2 MB
__device__ __align__(16) float g_hs[MROWS * HID];                // 2 MB
__device__ __align__(16) float g_part[SPLITK * MROWS * HID];     // 8 MB
__device__ __align__(16) __half g_wih_h[HID * VOCAB];            // 16.4 MB (fp16 W_ih)

__device__ __forceinline__ uint32_t pack_bf16(float a, float b) {
    __nv_bfloat162 t = __floats2bfloat162_rn(a, b);
    return *reinterpret_cast<uint32_t*>(&t);
}

__device__ __forceinline__ uint32_t pack_fp16(float a, float b) {
    __half2 t = __floats2half2_rn(a, b);
    return *reinterpret_cast<uint32_t*>(&t);
}

// fp16 split: hi = fp16(a), lo = fp16(a - float(hi)); hi+lo ~= a to ~2^-22
__device__ __forceinline__ void pack_fp16_split(float a, float b,
                                                uint32_t& hi, uint32_t& lo) {
    __half ah = __float2half_rn(a), bh = __float2half_rn(b);
    float alo = a - __half2float(ah);
    float blo = b - __half2float(bh);
    __half2 th; th.x = ah; th.y = bh;
    hi = *reinterpret_cast<uint32_t*>(&th);
    lo = pack_fp16(alo, blo);
}

// bf16 mma (GEMM2)
__device__ __forceinline__ void mma16816_bf16(float* d, const uint32_t* a, const uint32_t* b) {
    asm volatile(
        "mma.sync.aligned.m16n8k16.row.col.f32.bf16.bf16.f32 "
        "{%0,%1,%2,%3}, {%4,%5,%6,%7}, {%8,%9}, {%0,%1,%2,%3};\n"
        : "+f"(d[0]), "+f"(d[1]), "+f"(d[2]), "+f"(d[3])
        : "r"(a[0]), "r"(a[1]), "r"(a[2]), "r"(a[3]),
          "r"(b[0]), "r"(b[1]));
}

// fp16 mma (GEMM1)
__device__ __forceinline__ void mma16816_f16(float* d, const uint32_t* a, const uint32_t* b) {
    asm volatile(
        "mma.sync.aligned.m16n8k16.row.col.f32.f16.f16.f32 "
        "{%0,%1,%2,%3}, {%4,%5,%6,%7}, {%8,%9}, {%0,%1,%2,%3};\n"
        : "+f"(d[0]), "+f"(d[1]), "+f"(d[2]), "+f"(d[3])
        : "r"(a[0]), "r"(a[1]), "r"(a[2]), "r"(a[3]),
          "r"(b[0]), "r"(b[1]));
}

// packed f32x2 helpers (Blackwell FFMA2)
__device__ __forceinline__ ull pk2(float x, float y) {
    ull r; asm("mov.b64 %0, {%1, %2};" : "=l"(r) : "f"(x), "f"(y)); return r;
}
__device__ __forceinline__ void ffma2(ull& d, ull a, ull b) {
    asm("fma.rn.f32x2 %0, %1, %2, %3;" : "=l"(d) : "l"(a), "l"(b), "l"(d));
}
__device__ __forceinline__ float2 upk2(ull v) {
    float2 f; asm("mov.b64 {%0, %1}, %2;" : "=f"(f.x), "=f"(f.y) : "l"(v)); return f;
}

// ---------------------------------------------------------------------------
// Prep: W_ih fp32 -> fp16, elementwise.
// ---------------------------------------------------------------------------
__global__ __launch_bounds__(256) void prep_wih_kernel(const float* __restrict__ W)
{
    int idx = (blockIdx.x * 256 + threadIdx.x) * 4;
    float4 v = *reinterpret_cast<const float4*>(W + idx);
    uint2 h = make_uint2(pack_fp16(v.x, v.y), pack_fp16(v.z, v.w));
    *reinterpret_cast<uint2*>(g_wih_h + idx) = h;
}

// ---------------------------------------------------------------------------
// GEMM1 split-K, 2-term fp16 A-split: part[z] = A_chunk * B_chunk^T
// A fp32 (input_seq) split hi/lo fp16 in smem; B fp16 (preconverted W_ih).
// acc += A_hi*B + A_lo*B  (B-side fp16 quantization is the only error)
// ---------------------------------------------------------------------------
__global__ __launch_bounds__(256, 2) void gemm1_splitk_kernel(
    const float* __restrict__ A, float* __restrict__ part)
{
    constexpr int BM = 64, BN = 128, BK = 32;
    constexpr int SAW = 17;
    const int K = VOCAB, N = HID;

    __shared__ uint32_t As[2][BM][SAW];
    __shared__ uint32_t Bs[BN][SAW];

    const int tid = threadIdx.x;
    const int rowTile = blockIdx.x * BM;
    const int colTile = blockIdx.y * BN;
    const int kbase   = blockIdx.z * KCHUNK;
    const int warp = tid >> 5, lane = tid & 31;
    const int wm = warp % 2, wn = warp / 2;
    const int g = lane >> 2, tg = lane & 3;

    float acc[2][4][4];
    #pragma unroll
    for (int i = 0; i < 2; i++)
        #pragma unroll
        for (int j = 0; j < 4; j++)
            #pragma unroll
            for (int u = 0; u < 4; u++) acc[i][j][u] = 0.f;

    float4 aReg[2];
    uint4  bReg[2];

    #pragma unroll
    for (int i = 0; i < 2; i++) {
        int idx = tid + i * 256; int r = idx >> 3, q = idx & 7;
        aReg[i] = *reinterpret_cast<const float4*>(
            A + (size_t)(rowTile + r) * K + kbase + q * 4);
    }
    #pragma unroll
    for (int i = 0; i < 2; i++) {
        int idx = tid + i * 256; int r = idx >> 2, q = idx & 3;
        size_t off = (size_t)(colTile + r) * K + kbase + q * 8;
        bReg[i] = *reinterpret_cast<const uint4*>(g_wih_h + off);
    }

    for (int k0 = 0; k0 < KCHUNK; k0 += BK) {
        #pragma unroll
        for (int i = 0; i < 2; i++) {
            int idx = tid + i * 256; int r = idx >> 3, q = idx & 7;
            uint32_t h0, l0, h1, l1;
            pack_fp16_split(aReg[i].x, aReg[i].y, h0, l0);
            pack_fp16_split(aReg[i].z, aReg[i].w, h1, l1);
            As[0][r][q * 2] = h0; As[0][r][q * 2 + 1] = h1;
            As[1][r][q * 2] = l0; As[1][r][q * 2 + 1] = l1;
        }
        #pragma unroll
        for (int i = 0; i < 2; i++) {
            int idx = tid + i * 256; int r = idx >> 2, q = idx & 3;
            Bs[r][q * 4 + 0] = bReg[i].x; Bs[r][q * 4 + 1] = bReg[i].y;
            Bs[r][q * 4 + 2] = bReg[i].z; Bs[r][q * 4 + 3] = bReg[i].w;
        }
        __syncthreads();

        if (k0 + BK < KCHUNK) {
            #pragma unroll
            for (int i = 0; i < 2; i++) {
                int idx = tid + i * 256; int r = idx >> 3, q = idx & 7;
                aReg[i] = *reinterpret_cast<const float4*>(
                    A + (size_t)(rowTile + r) * K + kbase + (k0 + BK) + q * 4);
            }
            #pragma unroll
            for (int i = 0; i < 2; i++) {
                int idx = tid + i * 256; int r = idx >> 2, q = idx & 3;
                size_t off = (size_t)(colTile + r) * K + kbase + (k0 + BK) + q * 8;
                bReg[i] = *reinterpret_cast<const uint4*>(g_wih_h + off);
            }
        }

        #pragma unroll
        for (int kt = 0; kt < 2; kt++) {
            const int kp = kt * 8;
            uint32_t afr[2][2][4];
            #pragma unroll
            for (int s = 0; s < 2; s++)
                #pragma unroll
                for (int fm = 0; fm < 2; fm++) {
                    int r = wm * 32 + fm * 16 + g;
                    afr[s][fm][0] = As[s][r][kp + tg];
                    afr[s][fm][1] = As[s][r + 8][kp + tg];
                    afr[s][fm][2] = As[s][r][kp + tg + 4];
                    afr[s][fm][3] = As[s][r + 8][kp + tg + 4];
                }
            uint32_t bfr[4][2];
            #pragma unroll
            for (int fn = 0; fn < 4; fn++) {
                int c = wn * 32 + fn * 8 + g;
                bfr[fn][0] = Bs[c][kp + tg];
                bfr[fn][1] = Bs[c][kp + tg + 4];
            }
            #pragma unroll
            for (int fm = 0; fm < 2; fm++)
                #pragma unroll
                for (int fn = 0; fn < 4; fn++) {
                    mma16816_f16(acc[fm][fn], afr[0][fm], bfr[fn]);  // hi*B
                    mma16816_f16(acc[fm][fn], afr[1][fm], bfr[fn]);  // lo*B
                }
        }
        __syncthreads();
    }

    float* out = part + (size_t)blockIdx.z * MROWS * HID;
    #pragma unroll
    for (int fm = 0; fm < 2; fm++)
        #pragma unroll
        for (int fn = 0; fn < 4; fn++) {
            int r = rowTile + wm * 32 + fm * 16 + g;
            int c = colTile + wn * 32 + fn * 8 + tg * 2;
            out[(size_t)r * N + c]           = acc[fm][fn][0];
            out[(size_t)r * N + c + 1]       = acc[fm][fn][1];
            out[(size_t)(r + 8) * N + c]     = acc[fm][fn][2];
            out[(size_t)(r + 8) * N + c + 1] = acc[fm][fn][3];
        }
}

// ---------------------------------------------------------------------------
// Reduce split-K partials + biases -> x_pre. Deterministic fixed-order sum.
// ---------------------------------------------------------------------------
__global__ __launch_bounds__(256) void reduce_xpre_kernel(
    const float* __restrict__ b_ih, const float* __restrict__ b_hh)
{
    const int idx4 = blockIdx.x * 256 + threadIdx.x;
    const int TOT4 = MROWS * HID / 4;
    const float4* p = reinterpret_cast<const float4*>(g_part);
    float4 v = p[idx4];
    #pragma unroll
    for (int z = 1; z < SPLITK; z++) {
        float4 w = p[idx4 + z * TOT4];
        v.x += w.x; v.y += w.y; v.z += w.z; v.w += w.w;
    }
    const int n4 = idx4 & (HID / 4 - 1);
    float4 b1 = reinterpret_cast<const float4*>(b_ih)[n4];
    float4 b2 = reinterpret_cast<const float4*>(b_hh)[n4];
    v.x += b1.x + b2.x; v.y += b1.y + b2.y;
    v.z += b1.z + b2.z; v.w += b1.w + b2.w;
    reinterpret_cast<float4*>(g_xpre)[idx4] = v;
}

// ---------------------------------------------------------------------------
// GEMM2: C[M,N] = A[M,K] * B[N,K]^T + bias (plain bf16, BM=128 x BN=128)
// ---------------------------------------------------------------------------
template<int BM, int BN, int BK, int WM, int WN>
__global__ __launch_bounds__(256) void gemm_bias_kernel(
    const float* __restrict__ A, const float* __restrict__ B,
    const float* __restrict__ bias0,
    float* __restrict__ C, int M, int N, int K)
{
    constexpr int TM = BM / WM, TN = BN / WN;
    constexpr int FM = TM / 16, FN = TN / 8;
    constexpr int SAW = BK / 2 + 1;
    constexpr int AITER = BM * BK / (4 * 256);
    constexpr int BITER = BN * BK / (4 * 256);

    __shared__ uint32_t As[BM][SAW];
    __shared__ uint32_t Bs[BN][SAW];

    const int tid     = threadIdx.x;
    const int rowTile = blockIdx.x * BM;
    const int colTile = blockIdx.y * BN;
    const int warp = tid >> 5, lane = tid & 31;
    const int wm = warp % WM, wn = warp / WM;
    const int g = lane >> 2, tg = lane & 3;

    float acc[FM][FN][4];
    #pragma unroll
    for (int i = 0; i < FM; i++)
        #pragma unroll
        for (int j = 0; j < FN; j++)
            #pragma unroll
            for (int u = 0; u < 4; u++) acc[i][j][u] = 0.f;

    float4 aReg[AITER], bReg[BITER];
    #pragma unroll
    for (int i = 0; i < AITER; i++) {
        int idx = tid + i * 256; int r = idx >> 3, q = idx & 7;
        aReg[i] = *reinterpret_cast<const float4*>(A + (size_t)(rowTile + r) * K + q * 4);
    }
    #pragma unroll
    for (int i = 0; i < BITER; i++) {
        int idx = tid + i * 256; int r = idx >> 3, q = idx & 7;
        bReg[i] = *reinterpret_cast<const float4*>(B + (size_t)(colTile + r) * K + q * 4);
    }

    for (int k0 = 0; k0 < K; k0 += BK) {
        #pragma unroll
        for (int i = 0; i < AITER; i++) {
            int idx = tid + i * 256; int r = idx >> 3, q = idx & 7;
            As[r][q * 2]     = pack_bf16(aReg[i].x, aReg[i].y);
            As[r][q * 2 + 1] = pack_bf16(aReg[i].z, aReg[i].w);
        }
        #pragma unroll
        for (int i = 0; i < BITER; i++) {
            int idx = tid + i * 256; int r = idx >> 3, q = idx & 7;
            Bs[r][q * 2]     = pack_bf16(bReg[i].x, bReg[i].y);
            Bs[r][q * 2 + 1] = pack_bf16(bReg[i].z, bReg[i].w);
        }
        __syncthreads();

        if (k0 + BK < K) {
            #pragma unroll
            for (int i = 0; i < AITER; i++) {
                int idx = tid + i * 256; int r = idx >> 3, q = idx & 7;
                aReg[i] = *reinterpret_cast<const float4*>(
                    A + (size_t)(rowTile + r) * K + (k0 + BK) + q * 4);
            }
            #pragma unroll
            for (int i = 0; i < BITER; i++) {
                int idx = tid + i * 256; int r = idx >> 3, q = idx & 7;
                bReg[i] = *reinterpret_cast<const float4*>(
                    B + (size_t)(colTile + r) * K + (k0 + BK) + q * 4);
            }
        }

        #pragma unroll
        for (int kt = 0; kt < BK / 16; kt++) {
            const int kp = kt * 8;
            uint32_t afr[FM][4];
            #pragma unroll
            for (int fm = 0; fm < FM; fm++) {
                int r = wm * TM + fm * 16 + g;
                afr[fm][0] = As[r][kp + tg];
                afr[fm][1] = As[r + 8][kp + tg];
                afr[fm][2] = As[r][kp + tg + 4];
                afr[fm][3] = As[r + 8][kp + tg + 4];
            }
            uint32_t bfr[FN][2];
            #pragma unroll
            for (int fn = 0; fn < FN; fn++) {
                int c = wn * TN + fn * 8 + g;
                bfr[fn][0] = Bs[c][kp + tg];
                bfr[fn][1] = Bs[c][kp + tg + 4];
            }
            #pragma unroll
            for (int fm = 0; fm < FM; fm++)
                #pragma unroll
                for (int fn = 0; fn < FN; fn++)
                    mma16816_bf16(acc[fm][fn], afr[fm], bfr[fn]);
        }
        __syncthreads();
    }

    #pragma unroll
    for (int fm = 0; fm < FM; fm++) {
        #pragma unroll
        for (int fn = 0; fn < FN; fn++) {
            int r = rowTile + wm * TM + fm * 16 + g;
            int c = colTile + wn * TN + fn * 8 + tg * 2;
            float b0v = bias0[c], b1v = bias0[c + 1];
            C[(size_t)r * N + c]           = acc[fm][fn][0] + b0v;
            C[(size_t)r * N + c + 1]       = acc[fm][fn][1] + b1v;
            C[(size_t)(r + 8) * N + c]     = acc[fm][fn][2] + b0v;
            C[(size_t)(r + 8) * N + c + 1] = acc[fm][fn][3] + b1v;
        }
    }
}

// ---------------------------------------------------------------------------
// Recurrence: one CTA per batch, 256 threads (thread i -> h_i).
// W_hh fp16 in smem, stride 132 u32/row (conflict-free LDS.128).
// Packed f32x2 FFMA2 accumulation; double-buffered h; ONE sync per step.
// ---------------------------------------------------------------------------
#define RNN_WSTRIDE 132
#define RNN_SMEM (256*RNN_WSTRIDE*4 + 2*256*4)

__global__ __launch_bounds__(256) void rnn_kernel(
    const float* __restrict__ W_hh, const float* __restrict__ h0,
    const float* __restrict__ xpre, float* __restrict__ hs,
    float* __restrict__ hlast)
{
    extern __shared__ uint32_t smem[];
    uint32_t* Wp = smem;                                        // [256][132]
    float* hb = reinterpret_cast<float*>(smem + 256 * RNN_WSTRIDE); // [2][256]
    const int tid = threadIdx.x, b = blockIdx.x;

    // load W_hh fp32 -> fp16 pairs, row i = weights for output i
    for (int idx = tid; idx < 256 * 128; idx += 256) {
        int r = idx >> 7, p = idx & 127;
        const float2 wv = *reinterpret_cast<const float2*>(W_hh + r * 256 + 2 * p);
        Wp[r * RNN_WSTRIDE + p] = pack_fp16(wv.x, wv.y);
    }
    hb[tid] = h0[b * HID + tid];
    __syncthreads();

    const float* xp = xpre + (size_t)b * SEQ * HID;
    float* hrow     = hs   + (size_t)b * SEQ * HID;
    const uint4* wrow4 = reinterpret_cast<const uint4*>(Wp + tid * RNN_WSTRIDE);

    float xnext = xp[tid];
    int cur = 0;
    for (int t = 0; t < SEQ; t++) {
        float xc = xnext;
        if (t + 1 < SEQ) xnext = xp[(t + 1) * HID + tid];
        const float4* h4 = reinterpret_cast<const float4*>(hb + cur * 256);

        ull a0 = pk2(0.f, 0.f), a1 = pk2(0.f, 0.f);
        ull a2 = pk2(0.f, 0.f), a3 = pk2(0.f, 0.f);
        #pragma unroll 16
        for (int c = 0; c < 32; c++) {          // 8 MACs per iter
            uint4 w = wrow4[c];
            float4 hA = h4[2 * c];              // broadcast
            float4 hB = h4[2 * c + 1];
            float2 w0 = __half22float2(*reinterpret_cast<__half2*>(&w.x));
            float2 w1 = __half22float2(*reinterpret_cast<__half2*>(&w.y));
            float2 w2 = __half22float2(*reinterpret_cast<__half2*>(&w.z));
            float2 w3 = __half22float2(*reinterpret_cast<__half2*>(&w.w));
            ffma2(a0, pk2(hA.x, hA.y), pk2(w0.x, w0.y));
            ffma2(a1, pk2(hA.z, hA.w), pk2(w1.x, w1.y));
            ffma2(a2, pk2(hB.x, hB.y), pk2(w2.x, w2.y));
            ffma2(a3, pk2(hB.z, hB.w), pk2(w3.x, w3.y));
        }
        float2 f0 = upk2(a0), f1 = upk2(a1), f2 = upk2(a2), f3 = upk2(a3);
        float sum = ((f0.x + f0.y) + (f1.x + f1.y))
                  + ((f2.x + f2.y) + (f3.x + f3.y));
        float hn = tanhf(xc + sum);

        hb[(cur ^ 1) * 256 + tid] = hn;   // write next buffer
        hrow[t * HID + tid] = hn;         // stream to gmem
        cur ^= 1;
        __syncthreads();                  // single barrier per step
    }
    if (hlast) hlast[b * HID + tid] = hb[cur * 256 + tid];
}

// ---------------------------------------------------------------------------
// In-place log_softmax over each row of d_out[2048, 32000].
// ---------------------------------------------------------------------------
__global__ __launch_bounds__(256) void logsoftmax_kernel(float* __restrict__ out)
{
    const int row = blockIdx.x;
    float* x = out + (size_t)row * VOCAB;
    float4* x4 = reinterpret_cast<float4*>(x);
    const int N4 = VOCAB / 4;
    const int tid = threadIdx.x;

    float m = -3.0e38f, s = 0.f;
    for (int j = tid; j < N4; j += 256) {
        float4 v = x4[j];
        float vals[4] = {v.x, v.y, v.z, v.w};
        #pragma unroll
        for (int u = 0; u < 4; u++) {
            float vv = vals[u];
            if (vv > m) { s = s * __expf(m - vv) + 1.f; m = vv; }
            else        { s += __expf(vv - m); }
        }
    }
    __shared__ float sm[256], ss[256];
    sm[tid] = m; ss[tid] = s;
    __syncthreads();
    for (int off = 128; off > 0; off >>= 1) {
        if (tid < off) {
            float m1 = sm[tid], s1 = ss[tid];
            float m2 = sm[tid + off], s2 = ss[tid + off];
            float mm = fmaxf(m1, m2);
            sm[tid] = mm;
            ss[tid] = s1 * __expf(m1 - mm) + s2 * __expf(m2 - mm);
        }
        __syncthreads();
    }
    const float L = sm[0] + logf(ss[0]);
    for (int j = tid; j < N4; j += 256) {
        float4 v = x4[j];
        v.x -= L; v.y -= L; v.z -= L; v.w -= L;
        x4[j] = v;
    }
}

// ---------------------------------------------------------------------------
extern "C" void kernel_launch(void* const* d_in, const int* in_sizes, int n_in,
                              void* d_out, int out_size)
{
    const float* input_seq = (const float*)d_in[0];
    const float* h0        = (const float*)d_in[1];
    const float* W_ih      = (const float*)d_in[2];
    const float* W_hh      = (const float*)d_in[3];
    const float* b_ih      = (const float*)d_in[4];
    const float* b_hh      = (const float*)d_in[5];
    const float* W_fc      = (const float*)d_in[6];
    const float* b_fc      = (const float*)d_in[7];
    float* out = (float*)d_out;

    float *xpre_ptr = nullptr, *hs_ptr = nullptr, *part_ptr = nullptr;
    cudaGetSymbolAddress((void**)&xpre_ptr, g_xpre);
    cudaGetSymbolAddress((void**)&hs_ptr, g_hs);
    cudaGetSymbolAddress((void**)&part_ptr, g_part);

    // 0) W_ih -> fp16
    prep_wih_kernel<<<HID * VOCAB / (256 * 4), 256>>>(W_ih);

    // 1) split-K GEMM1 (2-term fp16 A-split)
    gemm1_splitk_kernel<<<dim3(MROWS/64, HID/128, SPLITK), 256>>>(
        input_seq, part_ptr);

    // 1b) reduce partials + biases -> x_pre
    reduce_xpre_kernel<<<MROWS * HID / (4 * 256), 256>>>(b_ih, b_hh);

    // 2) recurrence
    cudaFuncSetAttribute(rnn_kernel,
                         cudaFuncAttributeMaxDynamicSharedMemorySize, RNN_SMEM);
    const long long logits_elems = (long long)MROWS * VOCAB;
    float* hlast = ((long long)out_size >= logits_elems + BATCH * HID)
                       ? out + (size_t)logits_elems : nullptr;
    rnn_kernel<<<BATCH, 256, RNN_SMEM>>>(W_hh, h0, xpre_ptr, hs_ptr, hlast);

    // 3) logits = hs @ W_fc^T + b_fc   (BM=128 x BN=128 tiles)
    gemm_bias_kernel<128,128,32,2,4><<<dim3(MROWS/128, VOCAB/128), 256>>>(
        hs_ptr, W_fc, b_fc, out, MROWS, VOCAB, HID);

    // 4) in-place log_softmax
    logsoftmax_kernel<<<MROWS, 256>>>(out);
}

// round 6
// speedup vs baseline: 2.0098x; 1.1411x over previous
#include <cuda_runtime.h>
#include <cuda_bf16.h>
#include <cuda_fp16.h>
#include <math.h>
#include <stdint.h>

#define VOCAB 32000
#define HID   256
#define BATCH 8
#define SEQ   256
#define MROWS (BATCH*SEQ)   // 2048
#define SPLITK 4
#define KCHUNK (VOCAB/SPLITK)  // 8000

// Scratch (no allocation allowed)
__device__ __align__(16) float g_xpre[MROWS * HID];              // 2 MB
__device__ __align__(16) float g_hs[MROWS * HID];                // 2 MB
__device__ __align__(16) float g_part[SPLITK * MROWS * HID];     // 8 MB
__device__ __align__(16) __half g_wih_h[HID * VOCAB];            // 16.4 MB

__device__ __forceinline__ uint32_t pack_bf16(float a, float b) {
    __nv_bfloat162 t = __floats2bfloat162_rn(a, b);
    return *reinterpret_cast<uint32_t*>(&t);
}

__device__ __forceinline__ uint32_t pack_fp16(float a, float b) {
    __half2 t = __floats2half2_rn(a, b);
    return *reinterpret_cast<uint32_t*>(&t);
}

// fp16 split: hi = fp16(a), lo = fp16(a - float(hi))
__device__ __forceinline__ void pack_fp16_split(float a, float b,
                                                uint32_t& hi, uint32_t& lo) {
    __half ah = __float2half_rn(a), bh = __float2half_rn(b);
    float alo = a - __half2float(ah);
    float blo = b - __half2float(bh);
    __half2 th; th.x = ah; th.y = bh;
    hi = *reinterpret_cast<uint32_t*>(&th);
    lo = pack_fp16(alo, blo);
}

__device__ __forceinline__ void mma16816_bf16(float* d, const uint32_t* a, const uint32_t* b) {
    asm volatile(
        "mma.sync.aligned.m16n8k16.row.col.f32.bf16.bf16.f32 "
        "{%0,%1,%2,%3}, {%4,%5,%6,%7}, {%8,%9}, {%0,%1,%2,%3};\n"
        : "+f"(d[0]), "+f"(d[1]), "+f"(d[2]), "+f"(d[3])
        : "r"(a[0]), "r"(a[1]), "r"(a[2]), "r"(a[3]),
          "r"(b[0]), "r"(b[1]));
}

__device__ __forceinline__ void mma16816_f16(float* d, const uint32_t* a,
                                             uint32_t b0, uint32_t b1) {
    asm volatile(
        "mma.sync.aligned.m16n8k16.row.col.f32.f16.f16.f32 "
        "{%0,%1,%2,%3}, {%4,%5,%6,%7}, {%8,%9}, {%0,%1,%2,%3};\n"
        : "+f"(d[0]), "+f"(d[1]), "+f"(d[2]), "+f"(d[3])
        : "r"(a[0]), "r"(a[1]), "r"(a[2]), "r"(a[3]),
          "r"(b0), "r"(b1));
}

__device__ __forceinline__ uint32_t smem_u32addr(const void* p) {
    uint32_t a;
    asm("{ .reg .u64 t; cvta.to.shared.u64 t, %1; cvt.u32.u64 %0, t; }"
        : "=r"(a) : "l"(p));
    return a;
}

__device__ __forceinline__ void ldmatrix_x4(uint32_t* r, uint32_t addr) {
    asm volatile("ldmatrix.sync.aligned.m8n8.x4.shared.b16 {%0,%1,%2,%3}, [%4];"
                 : "=r"(r[0]), "=r"(r[1]), "=r"(r[2]), "=r"(r[3]) : "r"(addr));
}

// ---------------------------------------------------------------------------
// Prep: W_ih fp32 -> fp16
// ---------------------------------------------------------------------------
__global__ __launch_bounds__(256) void prep_wih_kernel(const float* __restrict__ W)
{
    int idx = (blockIdx.x * 256 + threadIdx.x) * 4;
    float4 v = *reinterpret_cast<const float4*>(W + idx);
    uint2 h = make_uint2(pack_fp16(v.x, v.y), pack_fp16(v.z, v.w));
    *reinterpret_cast<uint2*>(g_wih_h + idx) = h;
}

// ---------------------------------------------------------------------------
// GEMM1 split-K, 2-term fp16 A-split (unchanged from R5)
// ---------------------------------------------------------------------------
__global__ __launch_bounds__(256, 2) void gemm1_splitk_kernel(
    const float* __restrict__ A, float* __restrict__ part)
{
    constexpr int BM = 64, BN = 128, BK = 32;
    constexpr int SAW = 17;
    const int K = VOCAB, N = HID;

    __shared__ uint32_t As[2][BM][SAW];
    __shared__ uint32_t Bs[BN][SAW];

    const int tid = threadIdx.x;
    const int rowTile = blockIdx.x * BM;
    const int colTile = blockIdx.y * BN;
    const int kbase   = blockIdx.z * KCHUNK;
    const int warp = tid >> 5, lane = tid & 31;
    const int wm = warp % 2, wn = warp / 2;
    const int g = lane >> 2, tg = lane & 3;

    float acc[2][4][4];
    #pragma unroll
    for (int i = 0; i < 2; i++)
        #pragma unroll
        for (int j = 0; j < 4; j++)
            #pragma unroll
            for (int u = 0; u < 4; u++) acc[i][j][u] = 0.f;

    float4 aReg[2];
    uint4  bReg[2];

    #pragma unroll
    for (int i = 0; i < 2; i++) {
        int idx = tid + i * 256; int r = idx >> 3, q = idx & 7;
        aReg[i] = *reinterpret_cast<const float4*>(
            A + (size_t)(rowTile + r) * K + kbase + q * 4);
    }
    #pragma unroll
    for (int i = 0; i < 2; i++) {
        int idx = tid + i * 256; int r = idx >> 2, q = idx & 3;
        size_t off = (size_t)(colTile + r) * K + kbase + q * 8;
        bReg[i] = *reinterpret_cast<const uint4*>(g_wih_h + off);
    }

    for (int k0 = 0; k0 < KCHUNK; k0 += BK) {
        #pragma unroll
        for (int i = 0; i < 2; i++) {
            int idx = tid + i * 256; int r = idx >> 3, q = idx & 7;
            uint32_t h0, l0, h1, l1;
            pack_fp16_split(aReg[i].x, aReg[i].y, h0, l0);
            pack_fp16_split(aReg[i].z, aReg[i].w, h1, l1);
            As[0][r][q * 2] = h0; As[0][r][q * 2 + 1] = h1;
            As[1][r][q * 2] = l0; As[1][r][q * 2 + 1] = l1;
        }
        #pragma unroll
        for (int i = 0; i < 2; i++) {
            int idx = tid + i * 256; int r = idx >> 2, q = idx & 3;
            Bs[r][q * 4 + 0] = bReg[i].x; Bs[r][q * 4 + 1] = bReg[i].y;
            Bs[r][q * 4 + 2] = bReg[i].z; Bs[r][q * 4 + 3] = bReg[i].w;
        }
        __syncthreads();

        if (k0 + BK < KCHUNK) {
            #pragma unroll
            for (int i = 0; i < 2; i++) {
                int idx = tid + i * 256; int r = idx >> 3, q = idx & 7;
                aReg[i] = *reinterpret_cast<const float4*>(
                    A + (size_t)(rowTile + r) * K + kbase + (k0 + BK) + q * 4);
            }
            #pragma unroll
            for (int i = 0; i < 2; i++) {
                int idx = tid + i * 256; int r = idx >> 2, q = idx & 3;
                size_t off = (size_t)(colTile + r) * K + kbase + (k0 + BK) + q * 8;
                bReg[i] = *reinterpret_cast<const uint4*>(g_wih_h + off);
            }
        }

        #pragma unroll
        for (int kt = 0; kt < 2; kt++) {
            const int kp = kt * 8;
            uint32_t afr[2][2][4];
            #pragma unroll
            for (int s = 0; s < 2; s++)
                #pragma unroll
                for (int fm = 0; fm < 2; fm++) {
                    int r = wm * 32 + fm * 16 + g;
                    afr[s][fm][0] = As[s][r][kp + tg];
                    afr[s][fm][1] = As[s][r + 8][kp + tg];
                    afr[s][fm][2] = As[s][r][kp + tg + 4];
                    afr[s][fm][3] = As[s][r + 8][kp + tg + 4];
                }
            uint32_t bfr[4][2];
            #pragma unroll
            for (int fn = 0; fn < 4; fn++) {
                int c = wn * 32 + fn * 8 + g;
                bfr[fn][0] = Bs[c][kp + tg];
                bfr[fn][1] = Bs[c][kp + tg + 4];
            }
            #pragma unroll
            for (int fm = 0; fm < 2; fm++)
                #pragma unroll
                for (int fn = 0; fn < 4; fn++) {
                    mma16816_f16(acc[fm][fn], afr[0][fm], bfr[fn][0], bfr[fn][1]);
                    mma16816_f16(acc[fm][fn], afr[1][fm], bfr[fn][0], bfr[fn][1]);
                }
        }
        __syncthreads();
    }

    float* out = part + (size_t)blockIdx.z * MROWS * HID;
    #pragma unroll
    for (int fm = 0; fm < 2; fm++)
        #pragma unroll
        for (int fn = 0; fn < 4; fn++) {
            int r = rowTile + wm * 32 + fm * 16 + g;
            int c = colTile + wn * 32 + fn * 8 + tg * 2;
            out[(size_t)r * N + c]           = acc[fm][fn][0];
            out[(size_t)r * N + c + 1]       = acc[fm][fn][1];
            out[(size_t)(r + 8) * N + c]     = acc[fm][fn][2];
            out[(size_t)(r + 8) * N + c + 1] = acc[fm][fn][3];
        }
}

// ---------------------------------------------------------------------------
// Reduce split-K partials + biases -> x_pre
// ---------------------------------------------------------------------------
__global__ __launch_bounds__(256) void reduce_xpre_kernel(
    const float* __restrict__ b_ih, const float* __restrict__ b_hh)
{
    const int idx4 = blockIdx.x * 256 + threadIdx.x;
    const int TOT4 = MROWS * HID / 4;
    const float4* p = reinterpret_cast<const float4*>(g_part);
    float4 v = p[idx4];
    #pragma unroll
    for (int z = 1; z < SPLITK; z++) {
        float4 w = p[idx4 + z * TOT4];
        v.x += w.x; v.y += w.y; v.z += w.z; v.w += w.w;
    }
    const int n4 = idx4 & (HID / 4 - 1);
    float4 b1 = reinterpret_cast<const float4*>(b_ih)[n4];
    float4 b2 = reinterpret_cast<const float4*>(b_hh)[n4];
    v.x += b1.x + b2.x; v.y += b1.y + b2.y;
    v.z += b1.z + b2.z; v.w += b1.w + b2.w;
    reinterpret_cast<float4*>(g_xpre)[idx4] = v;
}

// ---------------------------------------------------------------------------
// GEMM2 (plain bf16, 128x128 tiles) — unchanged
// ---------------------------------------------------------------------------
template<int BM, int BN, int BK, int WM, int WN>
__global__ __launch_bounds__(256) void gemm_bias_kernel(
    const float* __restrict__ A, const float* __restrict__ B,
    const float* __restrict__ bias0,
    float* __restrict__ C, int M, int N, int K)
{
    constexpr int TM = BM / WM, TN = BN / WN;
    constexpr int FM = TM / 16, FN = TN / 8;
    constexpr int SAW = BK / 2 + 1;
    constexpr int AITER = BM * BK / (4 * 256);
    constexpr int BITER = BN * BK / (4 * 256);

    __shared__ uint32_t As[BM][SAW];
    __shared__ uint32_t Bs[BN][SAW];

    const int tid     = threadIdx.x;
    const int rowTile = blockIdx.x * BM;
    const int colTile = blockIdx.y * BN;
    const int warp = tid >> 5, lane = tid & 31;
    const int wm = warp % WM, wn = warp / WM;
    const int g = lane >> 2, tg = lane & 3;

    float acc[FM][FN][4];
    #pragma unroll
    for (int i = 0; i < FM; i++)
        #pragma unroll
        for (int j = 0; j < FN; j++)
            #pragma unroll
            for (int u = 0; u < 4; u++) acc[i][j][u] = 0.f;

    float4 aReg[AITER], bReg[BITER];
    #pragma unroll
    for (int i = 0; i < AITER; i++) {
        int idx = tid + i * 256; int r = idx >> 3, q = idx & 7;
        aReg[i] = *reinterpret_cast<const float4*>(A + (size_t)(rowTile + r) * K + q * 4);
    }
    #pragma unroll
    for (int i = 0; i < BITER; i++) {
        int idx = tid + i * 256; int r = idx >> 3, q = idx & 7;
        bReg[i] = *reinterpret_cast<const float4*>(B + (size_t)(colTile + r) * K + q * 4);
    }

    for (int k0 = 0; k0 < K; k0 += BK) {
        #pragma unroll
        for (int i = 0; i < AITER; i++) {
            int idx = tid + i * 256; int r = idx >> 3, q = idx & 7;
            As[r][q * 2]     = pack_bf16(aReg[i].x, aReg[i].y);
            As[r][q * 2 + 1] = pack_bf16(aReg[i].z, aReg[i].w);
        }
        #pragma unroll
        for (int i = 0; i < BITER; i++) {
            int idx = tid + i * 256; int r = idx >> 3, q = idx & 7;
            Bs[r][q * 2]     = pack_bf16(bReg[i].x, bReg[i].y);
            Bs[r][q * 2 + 1] = pack_bf16(bReg[i].z, bReg[i].w);
        }
        __syncthreads();

        if (k0 + BK < K) {
            #pragma unroll
            for (int i = 0; i < AITER; i++) {
                int idx = tid + i * 256; int r = idx >> 3, q = idx & 7;
                aReg[i] = *reinterpret_cast<const float4*>(
                    A + (size_t)(rowTile + r) * K + (k0 + BK) + q * 4);
            }
            #pragma unroll
            for (int i = 0; i < BITER; i++) {
                int idx = tid + i * 256; int r = idx >> 3, q = idx & 7;
                bReg[i] = *reinterpret_cast<const float4*>(
                    B + (size_t)(colTile + r) * K + (k0 + BK) + q * 4);
            }
        }

        #pragma unroll
        for (int kt = 0; kt < BK / 16; kt++) {
            const int kp = kt * 8;
            uint32_t afr[FM][4];
            #pragma unroll
            for (int fm = 0; fm < FM; fm++) {
                int r = wm * TM + fm * 16 + g;
                afr[fm][0] = As[r][kp + tg];
                afr[fm][1] = As[r + 8][kp + tg];
                afr[fm][2] = As[r][kp + tg + 4];
                afr[fm][3] = As[r + 8][kp + tg + 4];
            }
            uint32_t bfr[FN][2];
            #pragma unroll
            for (int fn = 0; fn < FN; fn++) {
                int c = wn * TN + fn * 8 + g;
                bfr[fn][0] = Bs[c][kp + tg];
                bfr[fn][1] = Bs[c][kp + tg + 4];
            }
            #pragma unroll
            for (int fm = 0; fm < FM; fm++)
                #pragma unroll
                for (int fn = 0; fn < FN; fn++)
                    mma16816_bf16(acc[fm][fn], afr[fm], bfr[fn]);
        }
        __syncthreads();
    }

    #pragma unroll
    for (int fm = 0; fm < FM; fm++) {
        #pragma unroll
        for (int fn = 0; fn < FN; fn++) {
            int r = rowTile + wm * TM + fm * 16 + g;
            int c = colTile + wn * TN + fn * 8 + tg * 2;
            float b0v = bias0[c], b1v = bias0[c + 1];
            C[(size_t)r * N + c]           = acc[fm][fn][0] + b0v;
            C[(size_t)r * N + c + 1]       = acc[fm][fn][1] + b1v;
            C[(size_t)(r + 8) * N + c]     = acc[fm][fn][2] + b0v;
            C[(size_t)(r + 8) * N + c + 1] = acc[fm][fn][3] + b1v;
        }
    }
}

// ---------------------------------------------------------------------------
// Tensor-core recurrence. One CTA per batch, 8 warps.
// W_hh fp16 loaded to SMEM once (row stride 264 halves -> ldmatrix
// conflict-free), then ldmatrix'd into REGISTERS (A frags, loop-invariant).
// Per step: D = W @ h via mma.m16n8k16 (h fp16 replicated over the 8 N cols,
// built from 2 broadcast LDS per k-step), fp32 accum, tanh fp32.
// Mainloop per warp per step: 16 x (2 LDS + 2 HMMA) = 64 instrs.
// ---------------------------------------------------------------------------
#define WST 132                         // u32 per W row (= 264 halves, 528B)
#define RNN_SMEM (256*WST*4 + 2*256*2 + 2*256*4)

__global__ __launch_bounds__(256) void rnn_kernel(
    const float* __restrict__ W_hh, const float* __restrict__ h0,
    const float* __restrict__ xpre, float* __restrict__ hs,
    float* __restrict__ hlast)
{
    extern __shared__ uint32_t smem[];
    uint32_t* Wp   = smem;                                      // [256][132]
    __half*   h2   = reinterpret_cast<__half*>(smem + 256 * WST);  // [2][256]
    float*    xbuf = reinterpret_cast<float*>(h2 + 2 * 256);       // [2][256]

    const int tid = threadIdx.x, b = blockIdx.x;
    const int warp = tid >> 5, lane = tid & 31;
    const int g = lane >> 2, tg = lane & 3;

    // stage W_hh fp32 -> fp16 into padded layout (row r at u32 offset r*WST)
    for (int idx = tid; idx < 256 * 128; idx += 256) {
        int r = idx >> 7, p = idx & 127;
        const float2 wv = *reinterpret_cast<const float2*>(W_hh + r * 256 + 2 * p);
        Wp[r * WST + p] = pack_fp16(wv.x, wv.y);
    }
    const float* xp = xpre + (size_t)b * SEQ * HID;
    h2[tid]   = __float2half_rn(h0[b * HID + tid]);   // buffer 0
    xbuf[tid] = xp[tid];                              // x for t=0
    __syncthreads();

    // Load all A fragments into registers (loop-invariant W).
    // frag (mt, ks): rows warp*32+mt*16+(lane%16), halves ks*16+(lane/16)*8
    uint32_t A[2][16][4];
    {
        const uint32_t wbase = smem_u32addr(Wp);
        #pragma unroll
        for (int mt = 0; mt < 2; mt++)
            #pragma unroll
            for (int ks = 0; ks < 16; ks++) {
                int row = warp * 32 + mt * 16 + (lane & 15);
                int col = ks * 16 + (lane >> 4) * 8;          // in halves
                uint32_t addr = wbase + (uint32_t)(row * (WST * 4) + col * 2);
                ldmatrix_x4(A[mt][ks], addr);
            }
    }

    float* hrow = hs + (size_t)b * SEQ * HID;
    const int r0 = warp * 32 + g;        // first of this lane's 4 output rows
    const bool active = (tg == 0);

    float xnext = (SEQ > 1) ? xp[HID + tid] : 0.f;   // x for t=1
    int cur = 0;
    for (int t = 0; t < SEQ; t++) {
        float xn2 = (t + 2 < SEQ) ? xp[(t + 2) * HID + tid] : 0.f;

        const uint32_t* h2u =
            reinterpret_cast<const uint32_t*>(h2) + cur * 128;
        float acc0[4] = {0.f, 0.f, 0.f, 0.f};
        float acc1[4] = {0.f, 0.f, 0.f, 0.f};
        #pragma unroll
        for (int ks = 0; ks < 16; ks++) {
            uint32_t b0 = h2u[ks * 8 + tg];         // h[k..k+1]   (k=ks*16+2tg)
            uint32_t b1 = h2u[ks * 8 + 4 + tg];     // h[k+8..k+9]
            mma16816_f16(acc0, A[0][ks], b0, b1);
            mma16816_f16(acc1, A[1][ks], b0, b1);
        }

        const int nxt = cur ^ 1;
        if (active) {
            float y[4]   = {acc0[0], acc0[2], acc1[0], acc1[2]};
            int   rr[4]  = {r0, r0 + 8, r0 + 16, r0 + 24};
            #pragma unroll
            for (int u = 0; u < 4; u++) {
                float hn = tanhf(xbuf[cur * 256 + rr[u]] + y[u]);
                h2[nxt * 256 + rr[u]] = __float2half_rn(hn);
                hrow[t * HID + rr[u]] = hn;
                if (t == SEQ - 1 && hlast) hlast[b * HID + rr[u]] = hn;
            }
        }
        if (t + 1 < SEQ) xbuf[nxt * 256 + tid] = xnext;
        xnext = xn2;
        cur = nxt;
        __syncthreads();
    }
}

// ---------------------------------------------------------------------------
// In-place log_softmax over each row of d_out[2048, 32000].
// ---------------------------------------------------------------------------
__global__ __launch_bounds__(256) void logsoftmax_kernel(float* __restrict__ out)
{
    const int row = blockIdx.x;
    float* x = out + (size_t)row * VOCAB;
    float4* x4 = reinterpret_cast<float4*>(x);
    const int N4 = VOCAB / 4;
    const int tid = threadIdx.x;

    float m = -3.0e38f, s = 0.f;
    for (int j = tid; j < N4; j += 256) {
        float4 v = x4[j];
        float vals[4] = {v.x, v.y, v.z, v.w};
        #pragma unroll
        for (int u = 0; u < 4; u++) {
            float vv = vals[u];
            if (vv > m) { s = s * __expf(m - vv) + 1.f; m = vv; }
            else        { s += __expf(vv - m); }
        }
    }
    __shared__ float sm[256], ss[256];
    sm[tid] = m; ss[tid] = s;
    __syncthreads();
    for (int off = 128; off > 0; off >>= 1) {
        if (tid < off) {
            float m1 = sm[tid], s1 = ss[tid];
            float m2 = sm[tid + off], s2 = ss[tid + off];
            float mm = fmaxf(m1, m2);
            sm[tid] = mm;
            ss[tid] = s1 * __expf(m1 - mm) + s2 * __expf(m2 - mm);
        }
        __syncthreads();
    }
    const float L = sm[0] + logf(ss[0]);
    for (int j = tid; j < N4; j += 256) {
        float4 v = x4[j];
        v.x -= L; v.y -= L; v.z -= L; v.w -= L;
        x4[j] = v;
    }
}

// ---------------------------------------------------------------------------
extern "C" void kernel_launch(void* const* d_in, const int* in_sizes, int n_in,
                              void* d_out, int out_size)
{
    const float* input_seq = (const float*)d_in[0];
    const float* h0        = (const float*)d_in[1];
    const float* W_ih      = (const float*)d_in[2];
    const float* W_hh      = (const float*)d_in[3];
    const float* b_ih      = (const float*)d_in[4];
    const float* b_hh      = (const float*)d_in[5];
    const float* W_fc      = (const float*)d_in[6];
    const float* b_fc      = (const float*)d_in[7];
    float* out = (float*)d_out;

    float *xpre_ptr = nullptr, *hs_ptr = nullptr, *part_ptr = nullptr;
    cudaGetSymbolAddress((void**)&xpre_ptr, g_xpre);
    cudaGetSymbolAddress((void**)&hs_ptr, g_hs);
    cudaGetSymbolAddress((void**)&part_ptr, g_part);

    // 0) W_ih -> fp16
    prep_wih_kernel<<<HID * VOCAB / (256 * 4), 256>>>(W_ih);

    // 1) split-K GEMM1 (2-term fp16 A-split)
    gemm1_splitk_kernel<<<dim3(MROWS/64, HID/128, SPLITK), 256>>>(
        input_seq, part_ptr);

    // 1b) reduce partials + biases -> x_pre
    reduce_xpre_kernel<<<MROWS * HID / (4 * 256), 256>>>(b_ih, b_hh);

    // 2) recurrence (tensor-core, W in register fragments)
    cudaFuncSetAttribute(rnn_kernel,
                         cudaFuncAttributeMaxDynamicSharedMemorySize, RNN_SMEM);
    const long long logits_elems = (long long)MROWS * VOCAB;
    float* hlast = ((long long)out_size >= logits_elems + BATCH * HID)
                       ? out + (size_t)logits_elems : nullptr;
    rnn_kernel<<<BATCH, 256, RNN_SMEM>>>(W_hh, h0, xpre_ptr, hs_ptr, hlast);

    // 3) logits = hs @ W_fc^T + b_fc
    gemm_bias_kernel<128,128,32,2,4><<<dim3(MROWS/128, VOCAB/128), 256>>>(
        hs_ptr, W_fc, b_fc, out, MROWS, VOCAB, HID);

    // 4) in-place log_softmax
    logsoftmax_kernel<<<MROWS, 256>>>(out);
}

// round 7
// speedup vs baseline: 2.0780x; 1.0339x over previous
#include <cuda_runtime.h>
#include <cuda_bf16.h>
#include <cuda_fp16.h>
#include <math.h>
#include <stdint.h>

#define VOCAB 32000
#define HID   256
#define BATCH 8
#define SEQ   256
#define MROWS (BATCH*SEQ)   // 2048
#define SPLITK 4
#define KCHUNK (VOCAB/SPLITK)  // 8000

// Scratch (no allocation allowed)
__device__ __align__(16) float g_xpre[MROWS * HID];              // 2 MB
__device__ __align__(16) float g_hs[MROWS * HID];                // 2 MB
__device__ __align__(16) float g_part[SPLITK * MROWS * HID];     // 8 MB
__device__ __align__(16) __half g_wih_h[HID * VOCAB];            // 16.4 MB
__device__ __align__(16) __nv_bfloat16 g_wfc_b[VOCAB * HID];     // 16.4 MB

__device__ __forceinline__ uint32_t pack_bf16(float a, float b) {
    __nv_bfloat162 t = __floats2bfloat162_rn(a, b);
    return *reinterpret_cast<uint32_t*>(&t);
}

__device__ __forceinline__ uint32_t pack_fp16(float a, float b) {
    __half2 t = __floats2half2_rn(a, b);
    return *reinterpret_cast<uint32_t*>(&t);
}

// fp16 split: hi = fp16(a), lo = fp16(a - float(hi))
__device__ __forceinline__ void pack_fp16_split(float a, float b,
                                                uint32_t& hi, uint32_t& lo) {
    __half ah = __float2half_rn(a), bh = __float2half_rn(b);
    float alo = a - __half2float(ah);
    float blo = b - __half2float(bh);
    __half2 th; th.x = ah; th.y = bh;
    hi = *reinterpret_cast<uint32_t*>(&th);
    lo = pack_fp16(alo, blo);
}

__device__ __forceinline__ void mma16816_bf16(float* d, const uint32_t* a,
                                              uint32_t b0, uint32_t b1) {
    asm volatile(
        "mma.sync.aligned.m16n8k16.row.col.f32.bf16.bf16.f32 "
        "{%0,%1,%2,%3}, {%4,%5,%6,%7}, {%8,%9}, {%0,%1,%2,%3};\n"
        : "+f"(d[0]), "+f"(d[1]), "+f"(d[2]), "+f"(d[3])
        : "r"(a[0]), "r"(a[1]), "r"(a[2]), "r"(a[3]),
          "r"(b0), "r"(b1));
}

__device__ __forceinline__ void mma16816_f16(float* d, const uint32_t* a,
                                             uint32_t b0, uint32_t b1) {
    asm volatile(
        "mma.sync.aligned.m16n8k16.row.col.f32.f16.f16.f32 "
        "{%0,%1,%2,%3}, {%4,%5,%6,%7}, {%8,%9}, {%0,%1,%2,%3};\n"
        : "+f"(d[0]), "+f"(d[1]), "+f"(d[2]), "+f"(d[3])
        : "r"(a[0]), "r"(a[1]), "r"(a[2]), "r"(a[3]),
          "r"(b0), "r"(b1));
}

__device__ __forceinline__ uint32_t smem_u32addr(const void* p) {
    uint32_t a;
    asm("{ .reg .u64 t; cvta.to.shared.u64 t, %1; cvt.u32.u64 %0, t; }"
        : "=r"(a) : "l"(p));
    return a;
}

__device__ __forceinline__ void ldmatrix_x4(uint32_t* r, uint32_t addr) {
    asm volatile("ldmatrix.sync.aligned.m8n8.x4.shared.b16 {%0,%1,%2,%3}, [%4];"
                 : "=r"(r[0]), "=r"(r[1]), "=r"(r[2]), "=r"(r[3]) : "r"(addr));
}

// ---------------------------------------------------------------------------
// Prep kernels: W_ih fp32 -> fp16, W_fc fp32 -> bf16
// ---------------------------------------------------------------------------
__global__ __launch_bounds__(256) void prep_wih_kernel(const float* __restrict__ W)
{
    int idx = (blockIdx.x * 256 + threadIdx.x) * 4;
    float4 v = *reinterpret_cast<const float4*>(W + idx);
    uint2 h = make_uint2(pack_fp16(v.x, v.y), pack_fp16(v.z, v.w));
    *reinterpret_cast<uint2*>(g_wih_h + idx) = h;
}

__global__ __launch_bounds__(256) void prep_wfc_kernel(const float* __restrict__ W)
{
    int idx = (blockIdx.x * 256 + threadIdx.x) * 4;
    float4 v = *reinterpret_cast<const float4*>(W + idx);
    uint2 h = make_uint2(pack_bf16(v.x, v.y), pack_bf16(v.z, v.w));
    *reinterpret_cast<uint2*>(g_wfc_b + idx) = h;
}

// ---------------------------------------------------------------------------
// GEMM1 split-K, 2-term fp16 A-split (unchanged)
// ---------------------------------------------------------------------------
__global__ __launch_bounds__(256, 2) void gemm1_splitk_kernel(
    const float* __restrict__ A, float* __restrict__ part)
{
    constexpr int BM = 64, BN = 128, BK = 32;
    constexpr int SAW = 17;
    const int K = VOCAB, N = HID;

    __shared__ uint32_t As[2][BM][SAW];
    __shared__ uint32_t Bs[BN][SAW];

    const int tid = threadIdx.x;
    const int rowTile = blockIdx.x * BM;
    const int colTile = blockIdx.y * BN;
    const int kbase   = blockIdx.z * KCHUNK;
    const int warp = tid >> 5, lane = tid & 31;
    const int wm = warp % 2, wn = warp / 2;
    const int g = lane >> 2, tg = lane & 3;

    float acc[2][4][4];
    #pragma unroll
    for (int i = 0; i < 2; i++)
        #pragma unroll
        for (int j = 0; j < 4; j++)
            #pragma unroll
            for (int u = 0; u < 4; u++) acc[i][j][u] = 0.f;

    float4 aReg[2];
    uint4  bReg[2];

    #pragma unroll
    for (int i = 0; i < 2; i++) {
        int idx = tid + i * 256; int r = idx >> 3, q = idx & 7;
        aReg[i] = *reinterpret_cast<const float4*>(
            A + (size_t)(rowTile + r) * K + kbase + q * 4);
    }
    #pragma unroll
    for (int i = 0; i < 2; i++) {
        int idx = tid + i * 256; int r = idx >> 2, q = idx & 3;
        size_t off = (size_t)(colTile + r) * K + kbase + q * 8;
        bReg[i] = *reinterpret_cast<const uint4*>(g_wih_h + off);
    }

    for (int k0 = 0; k0 < KCHUNK; k0 += BK) {
        #pragma unroll
        for (int i = 0; i < 2; i++) {
            int idx = tid + i * 256; int r = idx >> 3, q = idx & 7;
            uint32_t h0, l0, h1, l1;
            pack_fp16_split(aReg[i].x, aReg[i].y, h0, l0);
            pack_fp16_split(aReg[i].z, aReg[i].w, h1, l1);
            As[0][r][q * 2] = h0; As[0][r][q * 2 + 1] = h1;
            As[1][r][q * 2] = l0; As[1][r][q * 2 + 1] = l1;
        }
        #pragma unroll
        for (int i = 0; i < 2; i++) {
            int idx = tid + i * 256; int r = idx >> 2, q = idx & 3;
            Bs[r][q * 4 + 0] = bReg[i].x; Bs[r][q * 4 + 1] = bReg[i].y;
            Bs[r][q * 4 + 2] = bReg[i].z; Bs[r][q * 4 + 3] = bReg[i].w;
        }
        __syncthreads();

        if (k0 + BK < KCHUNK) {
            #pragma unroll
            for (int i = 0; i < 2; i++) {
                int idx = tid + i * 256; int r = idx >> 3, q = idx & 7;
                aReg[i] = *reinterpret_cast<const float4*>(
                    A + (size_t)(rowTile + r) * K + kbase + (k0 + BK) + q * 4);
            }
            #pragma unroll
            for (int i = 0; i < 2; i++) {
                int idx = tid + i * 256; int r = idx >> 2, q = idx & 3;
                size_t off = (size_t)(colTile + r) * K + kbase + (k0 + BK) + q * 8;
                bReg[i] = *reinterpret_cast<const uint4*>(g_wih_h + off);
            }
        }

        #pragma unroll
        for (int kt = 0; kt < 2; kt++) {
            const int kp = kt * 8;
            uint32_t afr[2][2][4];
            #pragma unroll
            for (int s = 0; s < 2; s++)
                #pragma unroll
                for (int fm = 0; fm < 2; fm++) {
                    int r = wm * 32 + fm * 16 + g;
                    afr[s][fm][0] = As[s][r][kp + tg];
                    afr[s][fm][1] = As[s][r + 8][kp + tg];
                    afr[s][fm][2] = As[s][r][kp + tg + 4];
                    afr[s][fm][3] = As[s][r + 8][kp + tg + 4];
                }
            uint32_t bfr[4][2];
            #pragma unroll
            for (int fn = 0; fn < 4; fn++) {
                int c = wn * 32 + fn * 8 + g;
                bfr[fn][0] = Bs[c][kp + tg];
                bfr[fn][1] = Bs[c][kp + tg + 4];
            }
            #pragma unroll
            for (int fm = 0; fm < 2; fm++)
                #pragma unroll
                for (int fn = 0; fn < 4; fn++) {
                    mma16816_f16(acc[fm][fn], afr[0][fm], bfr[fn][0], bfr[fn][1]);
                    mma16816_f16(acc[fm][fn], afr[1][fm], bfr[fn][0], bfr[fn][1]);
                }
        }
        __syncthreads();
    }

    float* out = part + (size_t)blockIdx.z * MROWS * HID;
    #pragma unroll
    for (int fm = 0; fm < 2; fm++)
        #pragma unroll
        for (int fn = 0; fn < 4; fn++) {
            int r = rowTile + wm * 32 + fm * 16 + g;
            int c = colTile + wn * 32 + fn * 8 + tg * 2;
            out[(size_t)r * N + c]           = acc[fm][fn][0];
            out[(size_t)r * N + c + 1]       = acc[fm][fn][1];
            out[(size_t)(r + 8) * N + c]     = acc[fm][fn][2];
            out[(size_t)(r + 8) * N + c + 1] = acc[fm][fn][3];
        }
}

// ---------------------------------------------------------------------------
// Reduce split-K partials + biases -> x_pre
// ---------------------------------------------------------------------------
__global__ __launch_bounds__(256) void reduce_xpre_kernel(
    const float* __restrict__ b_ih, const float* __restrict__ b_hh)
{
    const int idx4 = blockIdx.x * 256 + threadIdx.x;
    const int TOT4 = MROWS * HID / 4;
    const float4* p = reinterpret_cast<const float4*>(g_part);
    float4 v = p[idx4];
    #pragma unroll
    for (int z = 1; z < SPLITK; z++) {
        float4 w = p[idx4 + z * TOT4];
        v.x += w.x; v.y += w.y; v.z += w.z; v.w += w.w;
    }
    const int n4 = idx4 & (HID / 4 - 1);
    float4 b1 = reinterpret_cast<const float4*>(b_ih)[n4];
    float4 b2 = reinterpret_cast<const float4*>(b_hh)[n4];
    v.x += b1.x + b2.x; v.y += b1.y + b2.y;
    v.z += b1.z + b2.z; v.w += b1.w + b2.w;
    reinterpret_cast<float4*>(g_xpre)[idx4] = v;
}

// ---------------------------------------------------------------------------
// GEMM2: logits = hs @ W_fc^T + b_fc. BM=128, BN=128, BK=32.
// A fp32 -> bf16 in-kernel; B preconverted bf16 (g_wfc_b).
// ---------------------------------------------------------------------------
__global__ __launch_bounds__(256) void gemm2_kernel(
    const float* __restrict__ A, const float* __restrict__ bias0,
    float* __restrict__ C)
{
    constexpr int BM = 128, BN = 128, BK = 32;
    constexpr int SAW = 17;
    const int N = VOCAB, K = HID;

    __shared__ uint32_t As[BM][SAW];
    __shared__ uint32_t Bs[BN][SAW];

    const int tid     = threadIdx.x;
    const int rowTile = blockIdx.x * BM;
    const int colTile = blockIdx.y * BN;
    const int warp = tid >> 5, lane = tid & 31;
    const int wm = warp % 2, wn = warp / 2;      // 2 x 4, TM=64, TN=32
    const int g = lane >> 2, tg = lane & 3;

    float acc[4][4][4];
    #pragma unroll
    for (int i = 0; i < 4; i++)
        #pragma unroll
        for (int j = 0; j < 4; j++)
            #pragma unroll
            for (int u = 0; u < 4; u++) acc[i][j][u] = 0.f;

    float4 aReg[4];
    uint4  bReg[2];
    #pragma unroll
    for (int i = 0; i < 4; i++) {
        int idx = tid + i * 256; int r = idx >> 3, q = idx & 7;
        aReg[i] = *reinterpret_cast<const float4*>(A + (size_t)(rowTile + r) * K + q * 4);
    }
    #pragma unroll
    for (int i = 0; i < 2; i++) {
        int idx = tid + i * 256; int r = idx >> 2, q = idx & 3;
        size_t off = (size_t)(colTile + r) * K + q * 8;
        bReg[i] = *reinterpret_cast<const uint4*>(g_wfc_b + off);
    }

    for (int k0 = 0; k0 < K; k0 += BK) {
        #pragma unroll
        for (int i = 0; i < 4; i++) {
            int idx = tid + i * 256; int r = idx >> 3, q = idx & 7;
            As[r][q * 2]     = pack_bf16(aReg[i].x, aReg[i].y);
            As[r][q * 2 + 1] = pack_bf16(aReg[i].z, aReg[i].w);
        }
        #pragma unroll
        for (int i = 0; i < 2; i++) {
            int idx = tid + i * 256; int r = idx >> 2, q = idx & 3;
            Bs[r][q * 4 + 0] = bReg[i].x; Bs[r][q * 4 + 1] = bReg[i].y;
            Bs[r][q * 4 + 2] = bReg[i].z; Bs[r][q * 4 + 3] = bReg[i].w;
        }
        __syncthreads();

        if (k0 + BK < K) {
            #pragma unroll
            for (int i = 0; i < 4; i++) {
                int idx = tid + i * 256; int r = idx >> 3, q = idx & 7;
                aReg[i] = *reinterpret_cast<const float4*>(
                    A + (size_t)(rowTile + r) * K + (k0 + BK) + q * 4);
            }
            #pragma unroll
            for (int i = 0; i < 2; i++) {
                int idx = tid + i * 256; int r = idx >> 2, q = idx & 3;
                size_t off = (size_t)(colTile + r) * K + (k0 + BK) + q * 8;
                bReg[i] = *reinterpret_cast<const uint4*>(g_wfc_b + off);
            }
        }

        #pragma unroll
        for (int kt = 0; kt < 2; kt++) {
            const int kp = kt * 8;
            uint32_t afr[4][4];
            #pragma unroll
            for (int fm = 0; fm < 4; fm++) {
                int r = wm * 64 + fm * 16 + g;
                afr[fm][0] = As[r][kp + tg];
                afr[fm][1] = As[r + 8][kp + tg];
                afr[fm][2] = As[r][kp + tg + 4];
                afr[fm][3] = As[r + 8][kp + tg + 4];
            }
            uint32_t bfr[4][2];
            #pragma unroll
            for (int fn = 0; fn < 4; fn++) {
                int c = wn * 32 + fn * 8 + g;
                bfr[fn][0] = Bs[c][kp + tg];
                bfr[fn][1] = Bs[c][kp + tg + 4];
            }
            #pragma unroll
            for (int fm = 0; fm < 4; fm++)
                #pragma unroll
                for (int fn = 0; fn < 4; fn++)
                    mma16816_bf16(acc[fm][fn], afr[fm], bfr[fn][0], bfr[fn][1]);
        }
        __syncthreads();
    }

    #pragma unroll
    for (int fm = 0; fm < 4; fm++) {
        #pragma unroll
        for (int fn = 0; fn < 4; fn++) {
            int r = rowTile + wm * 64 + fm * 16 + g;
            int c = colTile + wn * 32 + fn * 8 + tg * 2;
            float b0v = bias0[c], b1v = bias0[c + 1];
            C[(size_t)r * N + c]           = acc[fm][fn][0] + b0v;
            C[(size_t)r * N + c + 1]       = acc[fm][fn][1] + b1v;
            C[(size_t)(r + 8) * N + c]     = acc[fm][fn][2] + b0v;
            C[(size_t)(r + 8) * N + c + 1] = acc[fm][fn][3] + b1v;
        }
    }
}

// ---------------------------------------------------------------------------
// Tensor-core recurrence v3. One CTA per batch, 8 warps.
// - W_hh fp16 in registers (ldmatrix once, loop-invariant A fragments)
// - 4 independent accumulator chains per fragment (ks%4) -> HMMA dep depth 4
// - b-operand LDS all hoisted before the mma block
// - epilogue distributed: lane (g,tg) owns row warp*32+g+8*tg -> 1 tanh/lane
// - x prefetched from gmem 2 steps ahead into registers (no smem staging)
// ---------------------------------------------------------------------------
#define WST 132                         // u32 per W row (528B, ldmatrix-safe)
#define RNN_SMEM (256*WST*4 + 2*256*2)

__global__ __launch_bounds__(256) void rnn_kernel(
    const float* __restrict__ W_hh, const float* __restrict__ h0,
    const float* __restrict__ xpre, float* __restrict__ hs,
    float* __restrict__ hlast)
{
    extern __shared__ uint32_t smem[];
    uint32_t* Wp = smem;                                        // [256][132]
    __half*   h2 = reinterpret_cast<__half*>(smem + 256 * WST); // [2][256]

    const int tid = threadIdx.x, b = blockIdx.x;
    const int warp = tid >> 5, lane = tid & 31;
    const int g = lane >> 2, tg = lane & 3;

    for (int idx = tid; idx < 256 * 128; idx += 256) {
        int r = idx >> 7, p = idx & 127;
        const float2 wv = *reinterpret_cast<const float2*>(W_hh + r * 256 + 2 * p);
        Wp[r * WST + p] = pack_fp16(wv.x, wv.y);
    }
    h2[tid] = __float2half_rn(h0[b * HID + tid]);
    __syncthreads();

    uint32_t A[2][16][4];
    {
        const uint32_t wbase = smem_u32addr(Wp);
        #pragma unroll
        for (int mt = 0; mt < 2; mt++)
            #pragma unroll
            for (int ks = 0; ks < 16; ks++) {
                int row = warp * 32 + mt * 16 + (lane & 15);
                int col = ks * 16 + (lane >> 4) * 8;
                uint32_t addr = wbase + (uint32_t)(row * (WST * 4) + col * 2);
                ldmatrix_x4(A[mt][ks], addr);
            }
    }

    const float* xp = xpre + (size_t)b * SEQ * HID;
    float* hrow     = hs   + (size_t)b * SEQ * HID;
    const int r_own = warp * 32 + g + 8 * tg;   // this thread's output row

    float xc    = xp[r_own];
    float xnext = xp[HID + r_own];
    int cur = 0;
    for (int t = 0; t < SEQ; t++) {
        float xn2 = (t + 2 < SEQ) ? xp[(t + 2) * HID + r_own] : 0.f;

        const uint32_t* h2u = reinterpret_cast<const uint32_t*>(h2) + cur * 128;
        uint32_t bb0[16], bb1[16];
        #pragma unroll
        for (int ks = 0; ks < 16; ks++) {
            bb0[ks] = h2u[ks * 8 + tg];
            bb1[ks] = h2u[ks * 8 + 4 + tg];
        }

        float ac[2][4][4];
        #pragma unroll
        for (int i = 0; i < 2; i++)
            #pragma unroll
            for (int c = 0; c < 4; c++)
                #pragma unroll
                for (int u = 0; u < 4; u++) ac[i][c][u] = 0.f;

        #pragma unroll
        for (int ks = 0; ks < 16; ks++) {
            const int c = ks & 3;
            mma16816_f16(ac[0][c], A[0][ks], bb0[ks], bb1[ks]);
            mma16816_f16(ac[1][c], A[1][ks], bb0[ks], bb1[ks]);
        }

        // reduce the 4 chains; only elements [0] and [2] carry distinct rows
        float y00 = (ac[0][0][0] + ac[0][1][0]) + (ac[0][2][0] + ac[0][3][0]);
        float y02 = (ac[0][0][2] + ac[0][1][2]) + (ac[0][2][2] + ac[0][3][2]);
        float y10 = (ac[1][0][0] + ac[1][1][0]) + (ac[1][2][0] + ac[1][3][0]);
        float y12 = (ac[1][0][2] + ac[1][1][2]) + (ac[1][2][2] + ac[1][3][2]);
        float v = (tg == 0) ? y00 : (tg == 1) ? y02 : (tg == 2) ? y10 : y12;

        float hn = tanhf(xc + v);
        const int nxt = cur ^ 1;
        h2[nxt * 256 + r_own] = __float2half_rn(hn);
        hrow[t * HID + r_own] = hn;
        if (t == SEQ - 1 && hlast) hlast[b * HID + r_own] = hn;

        xc = xnext; xnext = xn2;
        cur = nxt;
        __syncthreads();
    }
}

// ---------------------------------------------------------------------------
// In-place log_softmax over each row of d_out[2048, 32000].
// ---------------------------------------------------------------------------
__global__ __launch_bounds__(256) void logsoftmax_kernel(float* __restrict__ out)
{
    const int row = blockIdx.x;
    float* x = out + (size_t)row * VOCAB;
    float4* x4 = reinterpret_cast<float4*>(x);
    const int N4 = VOCAB / 4;
    const int tid = threadIdx.x;

    float m = -3.0e38f, s = 0.f;
    for (int j = tid; j < N4; j += 256) {
        float4 v = x4[j];
        float vals[4] = {v.x, v.y, v.z, v.w};
        #pragma unroll
        for (int u = 0; u < 4; u++) {
            float vv = vals[u];
            if (vv > m) { s = s * __expf(m - vv) + 1.f; m = vv; }
            else        { s += __expf(vv - m); }
        }
    }
    __shared__ float sm[256], ss[256];
    sm[tid] = m; ss[tid] = s;
    __syncthreads();
    for (int off = 128; off > 0; off >>= 1) {
        if (tid < off) {
            float m1 = sm[tid], s1 = ss[tid];
            float m2 = sm[tid + off], s2 = ss[tid + off];
            float mm = fmaxf(m1, m2);
            sm[tid] = mm;
            ss[tid] = s1 * __expf(m1 - mm) + s2 * __expf(m2 - mm);
        }
        __syncthreads();
    }
    const float L = sm[0] + logf(ss[0]);
    for (int j = tid; j < N4; j += 256) {
        float4 v = x4[j];
        v.x -= L; v.y -= L; v.z -= L; v.w -= L;
        x4[j] = v;
    }
}

// ---------------------------------------------------------------------------
extern "C" void kernel_launch(void* const* d_in, const int* in_sizes, int n_in,
                              void* d_out, int out_size)
{
    const float* input_seq = (const float*)d_in[0];
    const float* h0        = (const float*)d_in[1];
    const float* W_ih      = (const float*)d_in[2];
    const float* W_hh      = (const float*)d_in[3];
    const float* b_ih      = (const float*)d_in[4];
    const float* b_hh      = (const float*)d_in[5];
    const float* W_fc      = (const float*)d_in[6];
    const float* b_fc      = (const float*)d_in[7];
    float* out = (float*)d_out;

    float *xpre_ptr = nullptr, *hs_ptr = nullptr, *part_ptr = nullptr;
    cudaGetSymbolAddress((void**)&xpre_ptr, g_xpre);
    cudaGetSymbolAddress((void**)&hs_ptr, g_hs);
    cudaGetSymbolAddress((void**)&part_ptr, g_part);

    // 0) weight preconversion
    prep_wih_kernel<<<HID * VOCAB / (256 * 4), 256>>>(W_ih);
    prep_wfc_kernel<<<VOCAB * HID / (256 * 4), 256>>>(W_fc);

    // 1) split-K GEMM1 (2-term fp16 A-split)
    gemm1_splitk_kernel<<<dim3(MROWS/64, HID/128, SPLITK), 256>>>(
        input_seq, part_ptr);

    // 1b) reduce partials + biases -> x_pre
    reduce_xpre_kernel<<<MROWS * HID / (4 * 256), 256>>>(b_ih, b_hh);

    // 2) recurrence (tensor-core v3)
    cudaFuncSetAttribute(rnn_kernel,
                         cudaFuncAttributeMaxDynamicSharedMemorySize, RNN_SMEM);
    const long long logits_elems = (long long)MROWS * VOCAB;
    float* hlast = ((long long)out_size >= logits_elems + BATCH * HID)
                       ? out + (size_t)logits_elems : nullptr;
    rnn_kernel<<<BATCH, 256, RNN_SMEM>>>(W_hh, h0, xpre_ptr, hs_ptr, hlast);

    // 3) logits = hs @ W_fc^T + b_fc (B preconverted bf16)
    gemm2_kernel<<<dim3(MROWS/128, VOCAB/128), 256>>>(hs_ptr, b_fc, out);

    // 4) in-place log_softmax
    logsoftmax_kernel<<<MROWS, 256>>>(out);
}

// round 8
// speedup vs baseline: 2.1041x; 1.0126x over previous
#include <cuda_runtime.h>
#include <cuda_bf16.h>
#include <cuda_fp16.h>
#include <math.h>
#include <stdint.h>

#define VOCAB 32000
#define HID   256
#define BATCH 8
#define SEQ   256
#define MROWS (BATCH*SEQ)   // 2048
#define SPLITK 4
#define KCHUNK (VOCAB/SPLITK)  // 8000
#define NCOLT (VOCAB/128)      // 250 column tiles in GEMM2

// Scratch (no allocation allowed)
__device__ __align__(16) float g_xpre[MROWS * HID];              // 2 MB
__device__ __align__(16) float g_hs[MROWS * HID];                // 2 MB
__device__ __align__(16) float g_part[SPLITK * MROWS * HID];     // 8 MB
__device__ __align__(16) __half g_wih_h[HID * VOCAB];            // 16.4 MB
__device__ __align__(16) __nv_bfloat16 g_wfc_b[VOCAB * HID];     // 16.4 MB
__device__ __align__(16) float2 g_softpart[NCOLT * MROWS];       // 4 MB (m,s)
__device__ __align__(16) float g_rowL[MROWS];                    // 8 KB

__device__ __forceinline__ uint32_t pack_bf16(float a, float b) {
    __nv_bfloat162 t = __floats2bfloat162_rn(a, b);
    return *reinterpret_cast<uint32_t*>(&t);
}

__device__ __forceinline__ uint32_t pack_fp16(float a, float b) {
    __half2 t = __floats2half2_rn(a, b);
    return *reinterpret_cast<uint32_t*>(&t);
}

// fp16 split: hi = fp16(a), lo = fp16(a - float(hi))
__device__ __forceinline__ void pack_fp16_split(float a, float b,
                                                uint32_t& hi, uint32_t& lo) {
    __half ah = __float2half_rn(a), bh = __float2half_rn(b);
    float alo = a - __half2float(ah);
    float blo = b - __half2float(bh);
    __half2 th; th.x = ah; th.y = bh;
    hi = *reinterpret_cast<uint32_t*>(&th);
    lo = pack_fp16(alo, blo);
}

__device__ __forceinline__ void mma16816_bf16(float* d, const uint32_t* a,
                                              uint32_t b0, uint32_t b1) {
    asm volatile(
        "mma.sync.aligned.m16n8k16.row.col.f32.bf16.bf16.f32 "
        "{%0,%1,%2,%3}, {%4,%5,%6,%7}, {%8,%9}, {%0,%1,%2,%3};\n"
        : "+f"(d[0]), "+f"(d[1]), "+f"(d[2]), "+f"(d[3])
        : "r"(a[0]), "r"(a[1]), "r"(a[2]), "r"(a[3]),
          "r"(b0), "r"(b1));
}

__device__ __forceinline__ void mma16816_f16(float* d, const uint32_t* a,
                                             uint32_t b0, uint32_t b1) {
    asm volatile(
        "mma.sync.aligned.m16n8k16.row.col.f32.f16.f16.f32 "
        "{%0,%1,%2,%3}, {%4,%5,%6,%7}, {%8,%9}, {%0,%1,%2,%3};\n"
        : "+f"(d[0]), "+f"(d[1]), "+f"(d[2]), "+f"(d[3])
        : "r"(a[0]), "r"(a[1]), "r"(a[2]), "r"(a[3]),
          "r"(b0), "r"(b1));
}

__device__ __forceinline__ uint32_t smem_u32addr(const void* p) {
    uint32_t a;
    asm("{ .reg .u64 t; cvta.to.shared.u64 t, %1; cvt.u32.u64 %0, t; }"
        : "=r"(a) : "l"(p));
    return a;
}

__device__ __forceinline__ void ldmatrix_x4(uint32_t* r, uint32_t addr) {
    asm volatile("ldmatrix.sync.aligned.m8n8.x4.shared.b16 {%0,%1,%2,%3}, [%4];"
                 : "=r"(r[0]), "=r"(r[1]), "=r"(r[2]), "=r"(r[3]) : "r"(addr));
}

// ---------------------------------------------------------------------------
// Prep kernels: W_ih fp32 -> fp16, W_fc fp32 -> bf16
// ---------------------------------------------------------------------------
__global__ __launch_bounds__(256) void prep_wih_kernel(const float* __restrict__ W)
{
    int idx = (blockIdx.x * 256 + threadIdx.x) * 4;
    float4 v = *reinterpret_cast<const float4*>(W + idx);
    uint2 h = make_uint2(pack_fp16(v.x, v.y), pack_fp16(v.z, v.w));
    *reinterpret_cast<uint2*>(g_wih_h + idx) = h;
}

__global__ __launch_bounds__(256) void prep_wfc_kernel(const float* __restrict__ W)
{
    int idx = (blockIdx.x * 256 + threadIdx.x) * 4;
    float4 v = *reinterpret_cast<const float4*>(W + idx);
    uint2 h = make_uint2(pack_bf16(v.x, v.y), pack_bf16(v.z, v.w));
    *reinterpret_cast<uint2*>(g_wfc_b + idx) = h;
}

// ---------------------------------------------------------------------------
// GEMM1 split-K, 2-term fp16 A-split (unchanged)
// ---------------------------------------------------------------------------
__global__ __launch_bounds__(256, 2) void gemm1_splitk_kernel(
    const float* __restrict__ A, float* __restrict__ part)
{
    constexpr int BM = 64, BN = 128, BK = 32;
    constexpr int SAW = 17;
    const int K = VOCAB, N = HID;

    __shared__ uint32_t As[2][BM][SAW];
    __shared__ uint32_t Bs[BN][SAW];

    const int tid = threadIdx.x;
    const int rowTile = blockIdx.x * BM;
    const int colTile = blockIdx.y * BN;
    const int kbase   = blockIdx.z * KCHUNK;
    const int warp = tid >> 5, lane = tid & 31;
    const int wm = warp % 2, wn = warp / 2;
    const int g = lane >> 2, tg = lane & 3;

    float acc[2][4][4];
    #pragma unroll
    for (int i = 0; i < 2; i++)
        #pragma unroll
        for (int j = 0; j < 4; j++)
            #pragma unroll
            for (int u = 0; u < 4; u++) acc[i][j][u] = 0.f;

    float4 aReg[2];
    uint4  bReg[2];

    #pragma unroll
    for (int i = 0; i < 2; i++) {
        int idx = tid + i * 256; int r = idx >> 3, q = idx & 7;
        aReg[i] = *reinterpret_cast<const float4*>(
            A + (size_t)(rowTile + r) * K + kbase + q * 4);
    }
    #pragma unroll
    for (int i = 0; i < 2; i++) {
        int idx = tid + i * 256; int r = idx >> 2, q = idx & 3;
        size_t off = (size_t)(colTile + r) * K + kbase + q * 8;
        bReg[i] = *reinterpret_cast<const uint4*>(g_wih_h + off);
    }

    for (int k0 = 0; k0 < KCHUNK; k0 += BK) {
        #pragma unroll
        for (int i = 0; i < 2; i++) {
            int idx = tid + i * 256; int r = idx >> 3, q = idx & 7;
            uint32_t h0, l0, h1, l1;
            pack_fp16_split(aReg[i].x, aReg[i].y, h0, l0);
            pack_fp16_split(aReg[i].z, aReg[i].w, h1, l1);
            As[0][r][q * 2] = h0; As[0][r][q * 2 + 1] = h1;
            As[1][r][q * 2] = l0; As[1][r][q * 2 + 1] = l1;
        }
        #pragma unroll
        for (int i = 0; i < 2; i++) {
            int idx = tid + i * 256; int r = idx >> 2, q = idx & 3;
            Bs[r][q * 4 + 0] = bReg[i].x; Bs[r][q * 4 + 1] = bReg[i].y;
            Bs[r][q * 4 + 2] = bReg[i].z; Bs[r][q * 4 + 3] = bReg[i].w;
        }
        __syncthreads();

        if (k0 + BK < KCHUNK) {
            #pragma unroll
            for (int i = 0; i < 2; i++) {
                int idx = tid + i * 256; int r = idx >> 3, q = idx & 7;
                aReg[i] = *reinterpret_cast<const float4*>(
                    A + (size_t)(rowTile + r) * K + kbase + (k0 + BK) + q * 4);
            }
            #pragma unroll
            for (int i = 0; i < 2; i++) {
                int idx = tid + i * 256; int r = idx >> 2, q = idx & 3;
                size_t off = (size_t)(colTile + r) * K + kbase + (k0 + BK) + q * 8;
                bReg[i] = *reinterpret_cast<const uint4*>(g_wih_h + off);
            }
        }

        #pragma unroll
        for (int kt = 0; kt < 2; kt++) {
            const int kp = kt * 8;
            uint32_t afr[2][2][4];
            #pragma unroll
            for (int s = 0; s < 2; s++)
                #pragma unroll
                for (int fm = 0; fm < 2; fm++) {
                    int r = wm * 32 + fm * 16 + g;
                    afr[s][fm][0] = As[s][r][kp + tg];
                    afr[s][fm][1] = As[s][r + 8][kp + tg];
                    afr[s][fm][2] = As[s][r][kp + tg + 4];
                    afr[s][fm][3] = As[s][r + 8][kp + tg + 4];
                }
            uint32_t bfr[4][2];
            #pragma unroll
            for (int fn = 0; fn < 4; fn++) {
                int c = wn * 32 + fn * 8 + g;
                bfr[fn][0] = Bs[c][kp + tg];
                bfr[fn][1] = Bs[c][kp + tg + 4];
            }
            #pragma unroll
            for (int fm = 0; fm < 2; fm++)
                #pragma unroll
                for (int fn = 0; fn < 4; fn++) {
                    mma16816_f16(acc[fm][fn], afr[0][fm], bfr[fn][0], bfr[fn][1]);
                    mma16816_f16(acc[fm][fn], afr[1][fm], bfr[fn][0], bfr[fn][1]);
                }
        }
        __syncthreads();
    }

    float* out = part + (size_t)blockIdx.z * MROWS * HID;
    #pragma unroll
    for (int fm = 0; fm < 2; fm++)
        #pragma unroll
        for (int fn = 0; fn < 4; fn++) {
            int r = rowTile + wm * 32 + fm * 16 + g;
            int c = colTile + wn * 32 + fn * 8 + tg * 2;
            out[(size_t)r * N + c]           = acc[fm][fn][0];
            out[(size_t)r * N + c + 1]       = acc[fm][fn][1];
            out[(size_t)(r + 8) * N + c]     = acc[fm][fn][2];
            out[(size_t)(r + 8) * N + c + 1] = acc[fm][fn][3];
        }
}

// ---------------------------------------------------------------------------
// Reduce split-K partials + biases -> x_pre
// ---------------------------------------------------------------------------
__global__ __launch_bounds__(256) void reduce_xpre_kernel(
    const float* __restrict__ b_ih, const float* __restrict__ b_hh)
{
    const int idx4 = blockIdx.x * 256 + threadIdx.x;
    const int TOT4 = MROWS * HID / 4;
    const float4* p = reinterpret_cast<const float4*>(g_part);
    float4 v = p[idx4];
    #pragma unroll
    for (int z = 1; z < SPLITK; z++) {
        float4 w = p[idx4 + z * TOT4];
        v.x += w.x; v.y += w.y; v.z += w.z; v.w += w.w;
    }
    const int n4 = idx4 & (HID / 4 - 1);
    float4 b1 = reinterpret_cast<const float4*>(b_ih)[n4];
    float4 b2 = reinterpret_cast<const float4*>(b_hh)[n4];
    v.x += b1.x + b2.x; v.y += b1.y + b2.y;
    v.z += b1.z + b2.z; v.w += b1.w + b2.w;
    reinterpret_cast<float4*>(g_xpre)[idx4] = v;
}

// ---------------------------------------------------------------------------
// GEMM2 + softmax partials: logits = hs @ W_fc^T + b_fc, and per-row
// (max, sumexp) over this CTA's 128-col tile -> g_softpart[colTile][row].
// ---------------------------------------------------------------------------
__global__ __launch_bounds__(256) void gemm2_kernel(
    const float* __restrict__ A, const float* __restrict__ bias0,
    float* __restrict__ C)
{
    constexpr int BM = 128, BN = 128, BK = 32;
    constexpr int SAW = 17;
    const int N = VOCAB, K = HID;

    __shared__ uint32_t As[BM][SAW];
    __shared__ uint32_t Bs[BN][SAW];
    __shared__ float2 spart[BM][4];      // per-row (m,s) per wn-warp

    const int tid     = threadIdx.x;
    const int rowTile = blockIdx.x * BM;
    const int colTile = blockIdx.y * BN;
    const int warp = tid >> 5, lane = tid & 31;
    const int wm = warp % 2, wn = warp / 2;      // 2 x 4, TM=64, TN=32
    const int g = lane >> 2, tg = lane & 3;

    float acc[4][4][4];
    #pragma unroll
    for (int i = 0; i < 4; i++)
        #pragma unroll
        for (int j = 0; j < 4; j++)
            #pragma unroll
            for (int u = 0; u < 4; u++) acc[i][j][u] = 0.f;

    float4 aReg[4];
    uint4  bReg[2];
    #pragma unroll
    for (int i = 0; i < 4; i++) {
        int idx = tid + i * 256; int r = idx >> 3, q = idx & 7;
        aReg[i] = *reinterpret_cast<const float4*>(A + (size_t)(rowTile + r) * K + q * 4);
    }
    #pragma unroll
    for (int i = 0; i < 2; i++) {
        int idx = tid + i * 256; int r = idx >> 2, q = idx & 3;
        size_t off = (size_t)(colTile + r) * K + q * 8;
        bReg[i] = *reinterpret_cast<const uint4*>(g_wfc_b + off);
    }

    for (int k0 = 0; k0 < K; k0 += BK) {
        #pragma unroll
        for (int i = 0; i < 4; i++) {
            int idx = tid + i * 256; int r = idx >> 3, q = idx & 7;
            As[r][q * 2]     = pack_bf16(aReg[i].x, aReg[i].y);
            As[r][q * 2 + 1] = pack_bf16(aReg[i].z, aReg[i].w);
        }
        #pragma unroll
        for (int i = 0; i < 2; i++) {
            int idx = tid + i * 256; int r = idx >> 2, q = idx & 3;
            Bs[r][q * 4 + 0] = bReg[i].x; Bs[r][q * 4 + 1] = bReg[i].y;
            Bs[r][q * 4 + 2] = bReg[i].z; Bs[r][q * 4 + 3] = bReg[i].w;
        }
        __syncthreads();

        if (k0 + BK < K) {
            #pragma unroll
            for (int i = 0; i < 4; i++) {
                int idx = tid + i * 256; int r = idx >> 3, q = idx & 7;
                aReg[i] = *reinterpret_cast<const float4*>(
                    A + (size_t)(rowTile + r) * K + (k0 + BK) + q * 4);
            }
            #pragma unroll
            for (int i = 0; i < 2; i++) {
                int idx = tid + i * 256; int r = idx >> 2, q = idx & 3;
                size_t off = (size_t)(colTile + r) * K + (k0 + BK) + q * 8;
                bReg[i] = *reinterpret_cast<const uint4*>(g_wfc_b + off);
            }
        }

        #pragma unroll
        for (int kt = 0; kt < 2; kt++) {
            const int kp = kt * 8;
            uint32_t afr[4][4];
            #pragma unroll
            for (int fm = 0; fm < 4; fm++) {
                int r = wm * 64 + fm * 16 + g;
                afr[fm][0] = As[r][kp + tg];
                afr[fm][1] = As[r + 8][kp + tg];
                afr[fm][2] = As[r][kp + tg + 4];
                afr[fm][3] = As[r + 8][kp + tg + 4];
            }
            uint32_t bfr[4][2];
            #pragma unroll
            for (int fn = 0; fn < 4; fn++) {
                int c = wn * 32 + fn * 8 + g;
                bfr[fn][0] = Bs[c][kp + tg];
                bfr[fn][1] = Bs[c][kp + tg + 4];
            }
            #pragma unroll
            for (int fm = 0; fm < 4; fm++)
                #pragma unroll
                for (int fn = 0; fn < 4; fn++)
                    mma16816_bf16(acc[fm][fn], afr[fm], bfr[fn][0], bfr[fn][1]);
        }
        __syncthreads();
    }

    // epilogue: add bias, write logits, accumulate per-row (m,s) partials
    #pragma unroll
    for (int fm = 0; fm < 4; fm++) {
        float m0 = -3.0e38f, s0 = 0.f;     // row r
        float m1 = -3.0e38f, s1 = 0.f;     // row r+8
        #pragma unroll
        for (int fn = 0; fn < 4; fn++) {
            int r = rowTile + wm * 64 + fm * 16 + g;
            int c = colTile + wn * 32 + fn * 8 + tg * 2;
            float b0v = bias0[c], b1v = bias0[c + 1];
            float v0 = acc[fm][fn][0] + b0v;
            float v1 = acc[fm][fn][1] + b1v;
            float v2 = acc[fm][fn][2] + b0v;
            float v3 = acc[fm][fn][3] + b1v;
            C[(size_t)r * N + c]           = v0;
            C[(size_t)r * N + c + 1]       = v1;
            C[(size_t)(r + 8) * N + c]     = v2;
            C[(size_t)(r + 8) * N + c + 1] = v3;
            // online (m,s) update for the 2+2 values
            float mm = fmaxf(v0, v1);
            if (mm > m0) { s0 = s0 * __expf(m0 - mm); m0 = mm; }
            s0 += __expf(v0 - m0) + __expf(v1 - m0);
            mm = fmaxf(v2, v3);
            if (mm > m1) { s1 = s1 * __expf(m1 - mm); m1 = mm; }
            s1 += __expf(v2 - m1) + __expf(v3 - m1);
        }
        // quad reduce over tg (lanes g*4 .. g*4+3)
        #pragma unroll
        for (int off = 1; off <= 2; off <<= 1) {
            float mo = __shfl_xor_sync(0xffffffffu, m0, off);
            float so = __shfl_xor_sync(0xffffffffu, s0, off);
            float mm = fmaxf(m0, mo);
            s0 = s0 * __expf(m0 - mm) + so * __expf(mo - mm);
            m0 = mm;
            mo = __shfl_xor_sync(0xffffffffu, m1, off);
            so = __shfl_xor_sync(0xffffffffu, s1, off);
            mm = fmaxf(m1, mo);
            s1 = s1 * __expf(m1 - mm) + so * __expf(mo - mm);
            m1 = mm;
        }
        if (tg == 0) {
            int rl = wm * 64 + fm * 16 + g;
            spart[rl][wn]     = make_float2(m0, s0);
            spart[rl + 8][wn] = make_float2(m1, s1);
        }
    }
    __syncthreads();
    if (tid < BM) {
        float m = -3.0e38f, s = 0.f;
        #pragma unroll
        for (int w = 0; w < 4; w++) {
            float2 p = spart[tid][w];
            float mm = fmaxf(m, p.x);
            s = s * __expf(m - mm) + p.y * __expf(p.x - mm);
            m = mm;
        }
        g_softpart[(size_t)blockIdx.y * MROWS + rowTile + tid] = make_float2(m, s);
    }
}

// ---------------------------------------------------------------------------
// Combine per-colTile partials -> L[row] = m + log(s). Fixed order.
// ---------------------------------------------------------------------------
__global__ __launch_bounds__(256) void combine_L_kernel()
{
    const int r = blockIdx.x * 256 + threadIdx.x;   // 2048 threads
    float m = -3.0e38f, s = 0.f;
    for (int ct = 0; ct < NCOLT; ct++) {
        float2 p = g_softpart[(size_t)ct * MROWS + r];
        float mm = fmaxf(m, p.x);
        s = s * __expf(m - mm) + p.y * __expf(p.x - mm);
        m = mm;
    }
    g_rowL[r] = m + logf(s);
}

// ---------------------------------------------------------------------------
// Subtract L[row] in place (one CTA per row).
// ---------------------------------------------------------------------------
__global__ __launch_bounds__(256) void subtract_kernel(float* __restrict__ out)
{
    const int row = blockIdx.x;
    const float L = g_rowL[row];
    float4* x4 = reinterpret_cast<float4*>(out + (size_t)row * VOCAB);
    const int N4 = VOCAB / 4;
    for (int j = threadIdx.x; j < N4; j += 256) {
        float4 v = x4[j];
        v.x -= L; v.y -= L; v.z -= L; v.w -= L;
        x4[j] = v;
    }
}

// ---------------------------------------------------------------------------
// Tensor-core recurrence v4: like v3 but NO hoisted b arrays (inline LDS)
// to stay under the register cliff. 4 accumulator chains per fragment.
// ---------------------------------------------------------------------------
#define WST 132
#define RNN_SMEM (256*WST*4 + 2*256*2)

__global__ __launch_bounds__(256) void rnn_kernel(
    const float* __restrict__ W_hh, const float* __restrict__ h0,
    const float* __restrict__ xpre, float* __restrict__ hs,
    float* __restrict__ hlast)
{
    extern __shared__ uint32_t smem[];
    uint32_t* Wp = smem;                                        // [256][132]
    __half*   h2 = reinterpret_cast<__half*>(smem + 256 * WST); // [2][256]

    const int tid = threadIdx.x, b = blockIdx.x;
    const int warp = tid >> 5, lane = tid & 31;
    const int g = lane >> 2, tg = lane & 3;

    for (int idx = tid; idx < 256 * 128; idx += 256) {
        int r = idx >> 7, p = idx & 127;
        const float2 wv = *reinterpret_cast<const float2*>(W_hh + r * 256 + 2 * p);
        Wp[r * WST + p] = pack_fp16(wv.x, wv.y);
    }
    h2[tid] = __float2half_rn(h0[b * HID + tid]);
    __syncthreads();

    uint32_t A[2][16][4];
    {
        const uint32_t wbase = smem_u32addr(Wp);
        #pragma unroll
        for (int mt = 0; mt < 2; mt++)
            #pragma unroll
            for (int ks = 0; ks < 16; ks++) {
                int row = warp * 32 + mt * 16 + (lane & 15);
                int col = ks * 16 + (lane >> 4) * 8;
                uint32_t addr = wbase + (uint32_t)(row * (WST * 4) + col * 2);
                ldmatrix_x4(A[mt][ks], addr);
            }
    }

    const float* xp = xpre + (size_t)b * SEQ * HID;
    float* hrow     = hs   + (size_t)b * SEQ * HID;
    const int r_own = warp * 32 + g + 8 * tg;

    float xc    = xp[r_own];
    float xnext = xp[HID + r_own];
    int cur = 0;
    for (int t = 0; t < SEQ; t++) {
        float xn2 = (t + 2 < SEQ) ? xp[(t + 2) * HID + r_own] : 0.f;

        const uint32_t* h2u = reinterpret_cast<const uint32_t*>(h2) + cur * 128;

        float ac[2][4][4];
        #pragma unroll
        for (int i = 0; i < 2; i++)
            #pragma unroll
            for (int c = 0; c < 4; c++)
                #pragma unroll
                for (int u = 0; u < 4; u++) ac[i][c][u] = 0.f;

        #pragma unroll
        for (int ks = 0; ks < 16; ks++) {
            uint32_t b0 = h2u[ks * 8 + tg];
            uint32_t b1 = h2u[ks * 8 + 4 + tg];
            const int c = ks & 3;
            mma16816_f16(ac[0][c], A[0][ks], b0, b1);
            mma16816_f16(ac[1][c], A[1][ks], b0, b1);
        }

        float y00 = (ac[0][0][0] + ac[0][1][0]) + (ac[0][2][0] + ac[0][3][0]);
        float y02 = (ac[0][0][2] + ac[0][1][2]) + (ac[0][2][2] + ac[0][3][2]);
        float y10 = (ac[1][0][0] + ac[1][1][0]) + (ac[1][2][0] + ac[1][3][0]);
        float y12 = (ac[1][0][2] + ac[1][1][2]) + (ac[1][2][2] + ac[1][3][2]);
        float v = (tg == 0) ? y00 : (tg == 1) ? y02 : (tg == 2) ? y10 : y12;

        float hn = tanhf(xc + v);
        const int nxt = cur ^ 1;
        h2[nxt * 256 + r_own] = __float2half_rn(hn);
        hrow[t * HID + r_own] = hn;
        if (t == SEQ - 1 && hlast) hlast[b * HID + r_own] = hn;

        xc = xnext; xnext = xn2;
        cur = nxt;
        __syncthreads();
    }
}

// ---------------------------------------------------------------------------
extern "C" void kernel_launch(void* const* d_in, const int* in_sizes, int n_in,
                              void* d_out, int out_size)
{
    const float* input_seq = (const float*)d_in[0];
    const float* h0        = (const float*)d_in[1];
    const float* W_ih      = (const float*)d_in[2];
    const float* W_hh      = (const float*)d_in[3];
    const float* b_ih      = (const float*)d_in[4];
    const float* b_hh      = (const float*)d_in[5];
    const float* W_fc      = (const float*)d_in[6];
    const float* b_fc      = (const float*)d_in[7];
    float* out = (float*)d_out;

    float *xpre_ptr = nullptr, *hs_ptr = nullptr, *part_ptr = nullptr;
    cudaGetSymbolAddress((void**)&xpre_ptr, g_xpre);
    cudaGetSymbolAddress((void**)&hs_ptr, g_hs);
    cudaGetSymbolAddress((void**)&part_ptr, g_part);

    // 0) weight preconversion
    prep_wih_kernel<<<HID * VOCAB / (256 * 4), 256>>>(W_ih);
    prep_wfc_kernel<<<VOCAB * HID / (256 * 4), 256>>>(W_fc);

    // 1) split-K GEMM1 (2-term fp16 A-split)
    gemm1_splitk_kernel<<<dim3(MROWS/64, HID/128, SPLITK), 256>>>(
        input_seq, part_ptr);

    // 1b) reduce partials + biases -> x_pre
    reduce_xpre_kernel<<<MROWS * HID / (4 * 256), 256>>>(b_ih, b_hh);

    // 2) recurrence (tensor-core v4)
    cudaFuncSetAttribute(rnn_kernel,
                         cudaFuncAttributeMaxDynamicSharedMemorySize, RNN_SMEM);
    const long long logits_elems = (long long)MROWS * VOCAB;
    float* hlast = ((long long)out_size >= logits_elems + BATCH * HID)
                       ? out + (size_t)logits_elems : nullptr;
    rnn_kernel<<<BATCH, 256, RNN_SMEM>>>(W_hh, h0, xpre_ptr, hs_ptr, hlast);

    // 3) logits + per-tile softmax partials
    gemm2_kernel<<<dim3(MROWS/128, NCOLT), 256>>>(hs_ptr, b_fc, out);

    // 3b) combine partials -> L[row]
    combine_L_kernel<<<MROWS/256, 256>>>();

    // 4) subtract L in place
    subtract_kernel<<<MROWS, 256>>>(out);
}

// round 9
// speedup vs baseline: 2.3702x; 1.1264x over previous
#include <cuda_runtime.h>
#include <cuda_bf16.h>
#include <cuda_fp16.h>
#include <math.h>
#include <stdint.h>

#define VOCAB 32000
#define HID   256
#define BATCH 8
#define SEQ   256
#define MROWS (BATCH*SEQ)   // 2048
#define SPLITK 4
#define KCHUNK (VOCAB/SPLITK)  // 8000
#define NCOLT (VOCAB/128)      // 250 column tiles in GEMM2

// Scratch (no allocation allowed)
__device__ __align__(16) float g_xpre[MROWS * HID];              // 2 MB
__device__ __align__(16) float g_hs[MROWS * HID];                // 2 MB
__device__ __align__(16) float g_part[SPLITK * MROWS * HID];     // 8 MB
__device__ __align__(16) __half g_wih_h[HID * VOCAB];            // 16.4 MB
__device__ __align__(16) __nv_bfloat16 g_wfc_b[VOCAB * HID];     // 16.4 MB
__device__ __align__(16) float2 g_softpart[NCOLT * MROWS];       // 4 MB (m,s)
__device__ __align__(16) float g_rowL[MROWS];                    // 8 KB

__device__ __forceinline__ uint32_t pack_bf16(float a, float b) {
    __nv_bfloat162 t = __floats2bfloat162_rn(a, b);
    return *reinterpret_cast<uint32_t*>(&t);
}

__device__ __forceinline__ uint32_t pack_fp16(float a, float b) {
    __half2 t = __floats2half2_rn(a, b);
    return *reinterpret_cast<uint32_t*>(&t);
}

__device__ __forceinline__ void mma16816_bf16(float* d, const uint32_t* a,
                                              uint32_t b0, uint32_t b1) {
    asm volatile(
        "mma.sync.aligned.m16n8k16.row.col.f32.bf16.bf16.f32 "
        "{%0,%1,%2,%3}, {%4,%5,%6,%7}, {%8,%9}, {%0,%1,%2,%3};\n"
        : "+f"(d[0]), "+f"(d[1]), "+f"(d[2]), "+f"(d[3])
        : "r"(a[0]), "r"(a[1]), "r"(a[2]), "r"(a[3]),
          "r"(b0), "r"(b1));
}

__device__ __forceinline__ void mma16816_f16(float* d, const uint32_t* a,
                                             uint32_t b0, uint32_t b1) {
    asm volatile(
        "mma.sync.aligned.m16n8k16.row.col.f32.f16.f16.f32 "
        "{%0,%1,%2,%3}, {%4,%5,%6,%7}, {%8,%9}, {%0,%1,%2,%3};\n"
        : "+f"(d[0]), "+f"(d[1]), "+f"(d[2]), "+f"(d[3])
        : "r"(a[0]), "r"(a[1]), "r"(a[2]), "r"(a[3]),
          "r"(b0), "r"(b1));
}

__device__ __forceinline__ uint32_t smem_u32addr(const void* p) {
    uint32_t a;
    asm("{ .reg .u64 t; cvta.to.shared.u64 t, %1; cvt.u32.u64 %0, t; }"
        : "=r"(a) : "l"(p));
    return a;
}

__device__ __forceinline__ void ldmatrix_x4(uint32_t* r, uint32_t addr) {
    asm volatile("ldmatrix.sync.aligned.m8n8.x4.shared.b16 {%0,%1,%2,%3}, [%4];"
                 : "=r"(r[0]), "=r"(r[1]), "=r"(r[2]), "=r"(r[3]) : "r"(addr));
}

// ---------------------------------------------------------------------------
// Prep kernels: W_ih fp32 -> fp16, W_fc fp32 -> bf16
// ---------------------------------------------------------------------------
__global__ __launch_bounds__(256) void prep_wih_kernel(const float* __restrict__ W)
{
    int idx = (blockIdx.x * 256 + threadIdx.x) * 4;
    float4 v = *reinterpret_cast<const float4*>(W + idx);
    uint2 h = make_uint2(pack_fp16(v.x, v.y), pack_fp16(v.z, v.w));
    *reinterpret_cast<uint2*>(g_wih_h + idx) = h;
}

__global__ __launch_bounds__(256) void prep_wfc_kernel(const float* __restrict__ W)
{
    int idx = (blockIdx.x * 256 + threadIdx.x) * 4;
    float4 v = *reinterpret_cast<const float4*>(W + idx);
    uint2 h = make_uint2(pack_bf16(v.x, v.y), pack_bf16(v.z, v.w));
    *reinterpret_cast<uint2*>(g_wfc_b + idx) = h;
}

// ---------------------------------------------------------------------------
// GEMM1 split-K, SINGLE-term fp16: part[z] = fp16(A_chunk) * B_chunk^T.
// Both operands fp16 (2^-11 quantization each); measured error model says
// h_last lands ~5.7e-4 < 1e-3. Halves the HMMA work vs the 2-term split.
// BM=64, BN=128, BK=32, 8 warps WM=2 x WN=4.
// ---------------------------------------------------------------------------
__global__ __launch_bounds__(256, 2) void gemm1_splitk_kernel(
    const float* __restrict__ A, float* __restrict__ part)
{
    constexpr int BM = 64, BN = 128, BK = 32;
    constexpr int SAW = 17;
    const int K = VOCAB, N = HID;

    __shared__ uint32_t As[BM][SAW];
    __shared__ uint32_t Bs[BN][SAW];

    const int tid = threadIdx.x;
    const int rowTile = blockIdx.x * BM;
    const int colTile = blockIdx.y * BN;
    const int kbase   = blockIdx.z * KCHUNK;
    const int warp = tid >> 5, lane = tid & 31;
    const int wm = warp % 2, wn = warp / 2;
    const int g = lane >> 2, tg = lane & 3;

    float acc[2][4][4];
    #pragma unroll
    for (int i = 0; i < 2; i++)
        #pragma unroll
        for (int j = 0; j < 4; j++)
            #pragma unroll
            for (int u = 0; u < 4; u++) acc[i][j][u] = 0.f;

    float4 aReg[2];
    uint4  bReg[2];

    #pragma unroll
    for (int i = 0; i < 2; i++) {
        int idx = tid + i * 256; int r = idx >> 3, q = idx & 7;
        aReg[i] = *reinterpret_cast<const float4*>(
            A + (size_t)(rowTile + r) * K + kbase + q * 4);
    }
    #pragma unroll
    for (int i = 0; i < 2; i++) {
        int idx = tid + i * 256; int r = idx >> 2, q = idx & 3;
        size_t off = (size_t)(colTile + r) * K + kbase + q * 8;
        bReg[i] = *reinterpret_cast<const uint4*>(g_wih_h + off);
    }

    for (int k0 = 0; k0 < KCHUNK; k0 += BK) {
        #pragma unroll
        for (int i = 0; i < 2; i++) {
            int idx = tid + i * 256; int r = idx >> 3, q = idx & 7;
            As[r][q * 2]     = pack_fp16(aReg[i].x, aReg[i].y);
            As[r][q * 2 + 1] = pack_fp16(aReg[i].z, aReg[i].w);
        }
        #pragma unroll
        for (int i = 0; i < 2; i++) {
            int idx = tid + i * 256; int r = idx >> 2, q = idx & 3;
            Bs[r][q * 4 + 0] = bReg[i].x; Bs[r][q * 4 + 1] = bReg[i].y;
            Bs[r][q * 4 + 2] = bReg[i].z; Bs[r][q * 4 + 3] = bReg[i].w;
        }
        __syncthreads();

        if (k0 + BK < KCHUNK) {
            #pragma unroll
            for (int i = 0; i < 2; i++) {
                int idx = tid + i * 256; int r = idx >> 3, q = idx & 7;
                aReg[i] = *reinterpret_cast<const float4*>(
                    A + (size_t)(rowTile + r) * K + kbase + (k0 + BK) + q * 4);
            }
            #pragma unroll
            for (int i = 0; i < 2; i++) {
                int idx = tid + i * 256; int r = idx >> 2, q = idx & 3;
                size_t off = (size_t)(colTile + r) * K + kbase + (k0 + BK) + q * 8;
                bReg[i] = *reinterpret_cast<const uint4*>(g_wih_h + off);
            }
        }

        #pragma unroll
        for (int kt = 0; kt < 2; kt++) {
            const int kp = kt * 8;
            uint32_t afr[2][4];
            #pragma unroll
            for (int fm = 0; fm < 2; fm++) {
                int r = wm * 32 + fm * 16 + g;
                afr[fm][0] = As[r][kp + tg];
                afr[fm][1] = As[r + 8][kp + tg];
                afr[fm][2] = As[r][kp + tg + 4];
                afr[fm][3] = As[r + 8][kp + tg + 4];
            }
            uint32_t bfr[4][2];
            #pragma unroll
            for (int fn = 0; fn < 4; fn++) {
                int c = wn * 32 + fn * 8 + g;
                bfr[fn][0] = Bs[c][kp + tg];
                bfr[fn][1] = Bs[c][kp + tg + 4];
            }
            #pragma unroll
            for (int fm = 0; fm < 2; fm++)
                #pragma unroll
                for (int fn = 0; fn < 4; fn++)
                    mma16816_f16(acc[fm][fn], afr[fm], bfr[fn][0], bfr[fn][1]);
        }
        __syncthreads();
    }

    float* out = part + (size_t)blockIdx.z * MROWS * HID;
    #pragma unroll
    for (int fm = 0; fm < 2; fm++)
        #pragma unroll
        for (int fn = 0; fn < 4; fn++) {
            int r = rowTile + wm * 32 + fm * 16 + g;
            int c = colTile + wn * 32 + fn * 8 + tg * 2;
            out[(size_t)r * N + c]           = acc[fm][fn][0];
            out[(size_t)r * N + c + 1]       = acc[fm][fn][1];
            out[(size_t)(r + 8) * N + c]     = acc[fm][fn][2];
            out[(size_t)(r + 8) * N + c + 1] = acc[fm][fn][3];
        }
}

// ---------------------------------------------------------------------------
// Reduce split-K partials + biases -> x_pre
// ---------------------------------------------------------------------------
__global__ __launch_bounds__(256) void reduce_xpre_kernel(
    const float* __restrict__ b_ih, const float* __restrict__ b_hh)
{
    const int idx4 = blockIdx.x * 256 + threadIdx.x;
    const int TOT4 = MROWS * HID / 4;
    const float4* p = reinterpret_cast<const float4*>(g_part);
    float4 v = p[idx4];
    #pragma unroll
    for (int z = 1; z < SPLITK; z++) {
        float4 w = p[idx4 + z * TOT4];
        v.x += w.x; v.y += w.y; v.z += w.z; v.w += w.w;
    }
    const int n4 = idx4 & (HID / 4 - 1);
    float4 b1 = reinterpret_cast<const float4*>(b_ih)[n4];
    float4 b2 = reinterpret_cast<const float4*>(b_hh)[n4];
    v.x += b1.x + b2.x; v.y += b1.y + b2.y;
    v.z += b1.z + b2.z; v.w += b1.w + b2.w;
    reinterpret_cast<float4*>(g_xpre)[idx4] = v;
}

// ---------------------------------------------------------------------------
// GEMM2 + softmax partials: logits = hs @ W_fc^T + b_fc, and per-row
// (max, sumexp) over this CTA's 128-col tile -> g_softpart[colTile][row].
// ---------------------------------------------------------------------------
__global__ __launch_bounds__(256) void gemm2_kernel(
    const float* __restrict__ A, const float* __restrict__ bias0,
    float* __restrict__ C)
{
    constexpr int BM = 128, BN = 128, BK = 32;
    constexpr int SAW = 17;
    const int N = VOCAB, K = HID;

    __shared__ uint32_t As[BM][SAW];
    __shared__ uint32_t Bs[BN][SAW];
    __shared__ float2 spart[BM][4];      // per-row (m,s) per wn-warp

    const int tid     = threadIdx.x;
    const int rowTile = blockIdx.x * BM;
    const int colTile = blockIdx.y * BN;
    const int warp = tid >> 5, lane = tid & 31;
    const int wm = warp % 2, wn = warp / 2;      // 2 x 4, TM=64, TN=32
    const int g = lane >> 2, tg = lane & 3;

    float acc[4][4][4];
    #pragma unroll
    for (int i = 0; i < 4; i++)
        #pragma unroll
        for (int j = 0; j < 4; j++)
            #pragma unroll
            for (int u = 0; u < 4; u++) acc[i][j][u] = 0.f;

    float4 aReg[4];
    uint4  bReg[2];
    #pragma unroll
    for (int i = 0; i < 4; i++) {
        int idx = tid + i * 256; int r = idx >> 3, q = idx & 7;
        aReg[i] = *reinterpret_cast<const float4*>(A + (size_t)(rowTile + r) * K + q * 4);
    }
    #pragma unroll
    for (int i = 0; i < 2; i++) {
        int idx = tid + i * 256; int r = idx >> 2, q = idx & 3;
        size_t off = (size_t)(colTile + r) * K + q * 8;
        bReg[i] = *reinterpret_cast<const uint4*>(g_wfc_b + off);
    }

    for (int k0 = 0; k0 < K; k0 += BK) {
        #pragma unroll
        for (int i = 0; i < 4; i++) {
            int idx = tid + i * 256; int r = idx >> 3, q = idx & 7;
            As[r][q * 2]     = pack_bf16(aReg[i].x, aReg[i].y);
            As[r][q * 2 + 1] = pack_bf16(aReg[i].z, aReg[i].w);
        }
        #pragma unroll
        for (int i = 0; i < 2; i++) {
            int idx = tid + i * 256; int r = idx >> 2, q = idx & 3;
            Bs[r][q * 4 + 0] = bReg[i].x; Bs[r][q * 4 + 1] = bReg[i].y;
            Bs[r][q * 4 + 2] = bReg[i].z; Bs[r][q * 4 + 3] = bReg[i].w;
        }
        __syncthreads();

        if (k0 + BK < K) {
            #pragma unroll
            for (int i = 0; i < 4; i++) {
                int idx = tid + i * 256; int r = idx >> 3, q = idx & 7;
                aReg[i] = *reinterpret_cast<const float4*>(
                    A + (size_t)(rowTile + r) * K + (k0 + BK) + q * 4);
            }
            #pragma unroll
            for (int i = 0; i < 2; i++) {
                int idx = tid + i * 256; int r = idx >> 2, q = idx & 3;
                size_t off = (size_t)(colTile + r) * K + (k0 + BK) + q * 8;
                bReg[i] = *reinterpret_cast<const uint4*>(g_wfc_b + off);
            }
        }

        #pragma unroll
        for (int kt = 0; kt < 2; kt++) {
            const int kp = kt * 8;
            uint32_t afr[4][4];
            #pragma unroll
            for (int fm = 0; fm < 4; fm++) {
                int r = wm * 64 + fm * 16 + g;
                afr[fm][0] = As[r][kp + tg];
                afr[fm][1] = As[r + 8][kp + tg];
                afr[fm][2] = As[r][kp + tg + 4];
                afr[fm][3] = As[r + 8][kp + tg + 4];
            }
            uint32_t bfr[4][2];
            #pragma unroll
            for (int fn = 0; fn < 4; fn++) {
                int c = wn * 32 + fn * 8 + g;
                bfr[fn][0] = Bs[c][kp + tg];
                bfr[fn][1] = Bs[c][kp + tg + 4];
            }
            #pragma unroll
            for (int fm = 0; fm < 4; fm++)
                #pragma unroll
                for (int fn = 0; fn < 4; fn++)
                    mma16816_bf16(acc[fm][fn], afr[fm], bfr[fn][0], bfr[fn][1]);
        }
        __syncthreads();
    }

    // epilogue: add bias, write logits, accumulate per-row (m,s) partials
    #pragma unroll
    for (int fm = 0; fm < 4; fm++) {
        float m0 = -3.0e38f, s0 = 0.f;     // row r
        float m1 = -3.0e38f, s1 = 0.f;     // row r+8
        #pragma unroll
        for (int fn = 0; fn < 4; fn++) {
            int r = rowTile + wm * 64 + fm * 16 + g;
            int c = colTile + wn * 32 + fn * 8 + tg * 2;
            float b0v = bias0[c], b1v = bias0[c + 1];
            float v0 = acc[fm][fn][0] + b0v;
            float v1 = acc[fm][fn][1] + b1v;
            float v2 = acc[fm][fn][2] + b0v;
            float v3 = acc[fm][fn][3] + b1v;
            C[(size_t)r * N + c]           = v0;
            C[(size_t)r * N + c + 1]       = v1;
            C[(size_t)(r + 8) * N + c]     = v2;
            C[(size_t)(r + 8) * N + c + 1] = v3;
            float mm = fmaxf(v0, v1);
            if (mm > m0) { s0 = s0 * __expf(m0 - mm); m0 = mm; }
            s0 += __expf(v0 - m0) + __expf(v1 - m0);
            mm = fmaxf(v2, v3);
            if (mm > m1) { s1 = s1 * __expf(m1 - mm); m1 = mm; }
            s1 += __expf(v2 - m1) + __expf(v3 - m1);
        }
        #pragma unroll
        for (int off = 1; off <= 2; off <<= 1) {
            float mo = __shfl_xor_sync(0xffffffffu, m0, off);
            float so = __shfl_xor_sync(0xffffffffu, s0, off);
            float mm = fmaxf(m0, mo);
            s0 = s0 * __expf(m0 - mm) + so * __expf(mo - mm);
            m0 = mm;
            mo = __shfl_xor_sync(0xffffffffu, m1, off);
            so = __shfl_xor_sync(0xffffffffu, s1, off);
            mm = fmaxf(m1, mo);
            s1 = s1 * __expf(m1 - mm) + so * __expf(mo - mm);
            m1 = mm;
        }
        if (tg == 0) {
            int rl = wm * 64 + fm * 16 + g;
            spart[rl][wn]     = make_float2(m0, s0);
            spart[rl + 8][wn] = make_float2(m1, s1);
        }
    }
    __syncthreads();
    if (tid < BM) {
        float m = -3.0e38f, s = 0.f;
        #pragma unroll
        for (int w = 0; w < 4; w++) {
            float2 p = spart[tid][w];
            float mm = fmaxf(m, p.x);
            s = s * __expf(m - mm) + p.y * __expf(p.x - mm);
            m = mm;
        }
        g_softpart[(size_t)blockIdx.y * MROWS + rowTile + tid] = make_float2(m, s);
    }
}

// ---------------------------------------------------------------------------
// Combine per-colTile partials -> L[row] = m + log(s). Fixed order.
// ---------------------------------------------------------------------------
__global__ __launch_bounds__(256) void combine_L_kernel()
{
    const int r = blockIdx.x * 256 + threadIdx.x;
    float m = -3.0e38f, s = 0.f;
    for (int ct = 0; ct < NCOLT; ct++) {
        float2 p = g_softpart[(size_t)ct * MROWS + r];
        float mm = fmaxf(m, p.x);
        s = s * __expf(m - mm) + p.y * __expf(p.x - mm);
        m = mm;
    }
    g_rowL[r] = m + logf(s);
}

// ---------------------------------------------------------------------------
// Subtract L[row] in place (one CTA per row).
// ---------------------------------------------------------------------------
__global__ __launch_bounds__(256) void subtract_kernel(float* __restrict__ out)
{
    const int row = blockIdx.x;
    const float L = g_rowL[row];
    float4* x4 = reinterpret_cast<float4*>(out + (size_t)row * VOCAB);
    const int N4 = VOCAB / 4;
    for (int j = threadIdx.x; j < N4; j += 256) {
        float4 v = x4[j];
        v.x -= L; v.y -= L; v.z -= L; v.w -= L;
        x4[j] = v;
    }
}

// ---------------------------------------------------------------------------
// Tensor-core recurrence v4 (unchanged from R8)
// ---------------------------------------------------------------------------
#define WST 132
#define RNN_SMEM (256*WST*4 + 2*256*2)

__global__ __launch_bounds__(256) void rnn_kernel(
    const float* __restrict__ W_hh, const float* __restrict__ h0,
    const float* __restrict__ xpre, float* __restrict__ hs,
    float* __restrict__ hlast)
{
    extern __shared__ uint32_t smem[];
    uint32_t* Wp = smem;                                        // [256][132]
    __half*   h2 = reinterpret_cast<__half*>(smem + 256 * WST); // [2][256]

    const int tid = threadIdx.x, b = blockIdx.x;
    const int warp = tid >> 5, lane = tid & 31;
    const int g = lane >> 2, tg = lane & 3;

    for (int idx = tid; idx < 256 * 128; idx += 256) {
        int r = idx >> 7, p = idx & 127;
        const float2 wv = *reinterpret_cast<const float2*>(W_hh + r * 256 + 2 * p);
        Wp[r * WST + p] = pack_fp16(wv.x, wv.y);
    }
    h2[tid] = __float2half_rn(h0[b * HID + tid]);
    __syncthreads();

    uint32_t A[2][16][4];
    {
        const uint32_t wbase = smem_u32addr(Wp);
        #pragma unroll
        for (int mt = 0; mt < 2; mt++)
            #pragma unroll
            for (int ks = 0; ks < 16; ks++) {
                int row = warp * 32 + mt * 16 + (lane & 15);
                int col = ks * 16 + (lane >> 4) * 8;
                uint32_t addr = wbase + (uint32_t)(row * (WST * 4) + col * 2);
                ldmatrix_x4(A[mt][ks], addr);
            }
    }

    const float* xp = xpre + (size_t)b * SEQ * HID;
    float* hrow     = hs   + (size_t)b * SEQ * HID;
    const int r_own = warp * 32 + g + 8 * tg;

    float xc    = xp[r_own];
    float xnext = xp[HID + r_own];
    int cur = 0;
    for (int t = 0; t < SEQ; t++) {
        float xn2 = (t + 2 < SEQ) ? xp[(t + 2) * HID + r_own] : 0.f;

        const uint32_t* h2u = reinterpret_cast<const uint32_t*>(h2) + cur * 128;

        float ac[2][4][4];
        #pragma unroll
        for (int i = 0; i < 2; i++)
            #pragma unroll
            for (int c = 0; c < 4; c++)
                #pragma unroll
                for (int u = 0; u < 4; u++) ac[i][c][u] = 0.f;

        #pragma unroll
        for (int ks = 0; ks < 16; ks++) {
            uint32_t b0 = h2u[ks * 8 + tg];
            uint32_t b1 = h2u[ks * 8 + 4 + tg];
            const int c = ks & 3;
            mma16816_f16(ac[0][c], A[0][ks], b0, b1);
            mma16816_f16(ac[1][c], A[1][ks], b0, b1);
        }

        float y00 = (ac[0][0][0] + ac[0][1][0]) + (ac[0][2][0] + ac[0][3][0]);
        float y02 = (ac[0][0][2] + ac[0][1][2]) + (ac[0][2][2] + ac[0][3][2]);
        float y10 = (ac[1][0][0] + ac[1][1][0]) + (ac[1][2][0] + ac[1][3][0]);
        float y12 = (ac[1][0][2] + ac[1][1][2]) + (ac[1][2][2] + ac[1][3][2]);
        float v = (tg == 0) ? y00 : (tg == 1) ? y02 : (tg == 2) ? y10 : y12;

        float hn = tanhf(xc + v);
        const int nxt = cur ^ 1;
        h2[nxt * 256 + r_own] = __float2half_rn(hn);
        hrow[t * HID + r_own] = hn;
        if (t == SEQ - 1 && hlast) hlast[b * HID + r_own] = hn;

        xc = xnext; xnext = xn2;
        cur = nxt;
        __syncthreads();
    }
}

// ---------------------------------------------------------------------------
extern "C" void kernel_launch(void* const* d_in, const int* in_sizes, int n_in,
                              void* d_out, int out_size)
{
    const float* input_seq = (const float*)d_in[0];
    const float* h0        = (const float*)d_in[1];
    const float* W_ih      = (const float*)d_in[2];
    const float* W_hh      = (const float*)d_in[3];
    const float* b_ih      = (const float*)d_in[4];
    const float* b_hh      = (const float*)d_in[5];
    const float* W_fc      = (const float*)d_in[6];
    const float* b_fc      = (const float*)d_in[7];
    float* out = (float*)d_out;

    float *xpre_ptr = nullptr, *hs_ptr = nullptr, *part_ptr = nullptr;
    cudaGetSymbolAddress((void**)&xpre_ptr, g_xpre);
    cudaGetSymbolAddress((void**)&hs_ptr, g_hs);
    cudaGetSymbolAddress((void**)&part_ptr, g_part);

    // 0) weight preconversion
    prep_wih_kernel<<<HID * VOCAB / (256 * 4), 256>>>(W_ih);
    prep_wfc_kernel<<<VOCAB * HID / (256 * 4), 256>>>(W_fc);

    // 1) split-K GEMM1 (single-term fp16)
    gemm1_splitk_kernel<<<dim3(MROWS/64, HID/128, SPLITK), 256>>>(
        input_seq, part_ptr);

    // 1b) reduce partials + biases -> x_pre
    reduce_xpre_kernel<<<MROWS * HID / (4 * 256), 256>>>(b_ih, b_hh);

    // 2) recurrence (tensor-core v4)
    cudaFuncSetAttribute(rnn_kernel,
                         cudaFuncAttributeMaxDynamicSharedMemorySize, RNN_SMEM);
    const long long logits_elems = (long long)MROWS * VOCAB;
    float* hlast = ((long long)out_size >= logits_elems + BATCH * HID)
                       ? out + (size_t)logits_elems : nullptr;
    rnn_kernel<<<BATCH, 256, RNN_SMEM>>>(W_hh, h0, xpre_ptr, hs_ptr, hlast);

    // 3) logits + per-tile softmax partials
    gemm2_kernel<<<dim3(MROWS/128, NCOLT), 256>>>(hs_ptr, b_fc, out);

    // 3b) combine partials -> L[row]
    combine_L_kernel<<<MROWS/256, 256>>>();

    // 4) subtract L in place
    subtract_kernel<<<MROWS, 256>>>(out);
}